// round 10
// baseline (speedup 1.0000x reference)
#include <cuda_runtime.h>
#include <cuda_bf16.h>
#include <cstdint>

// Problem constants
#define BB 4
#define TT 512
#define HH 256
#define EE 256
#define VV 32000
#define BT (BB*TT)          // 2048

// ---------------- device scratch (no cudaMalloc allowed) ----------------
__device__ float g_xp[BT * 768];          // [B*T, 3H]
__device__ float g_combined[BT * 512];    // [B*T, 2H]
__device__ float g_q[BT * HH];
__device__ float g_k[BT * HH];
__device__ float g_h[2][BB * HH];
__device__ int g_flags[32];               // per-CTA step flags for the GRU barrier

// split-bf16 operands for the HMMA FC
__device__ __align__(256) __nv_bfloat16 g_Whi[(size_t)VV * 512];
__device__ __align__(256) __nv_bfloat16 g_Wlo[(size_t)VV * 512];
__device__ __align__(256) __nv_bfloat16 g_Ahi[(size_t)BT * 512];
__device__ __align__(256) __nv_bfloat16 g_Alo[(size_t)BT * 512];

typedef unsigned long long u64;

__device__ __forceinline__ float tanh_fast(float x) {
    float y; asm("tanh.approx.f32 %0, %1;" : "=f"(y) : "f"(x)); return y;
}
__device__ __forceinline__ uint32_t smem_u32(const void* p) {
    uint32_t a;
    asm("{ .reg .u64 t; cvta.to.shared.u64 t, %1; cvt.u32.u64 %0, t; }" : "=r"(a) : "l"(p));
    return a;
}

// ---------------- init: h0 <- input h, reset barrier flags ----------------
__global__ void init_kernel(const float* __restrict__ h_in) {
    int t = threadIdx.x;
    if (t < BB * HH) g_h[0][t] = h_in[t];
    if (t < 32) g_flags[t] = 0;
}

// ---------------- generic small GEMM: C[M,N] = A[M,K] @ B[N,K]^T + bias ----------------
__global__ void __launch_bounds__(256) gemm_nt(
    const float* __restrict__ A, int lda, const int* __restrict__ idx,
    const float* __restrict__ B, int K,
    const float* __restrict__ bias, float* __restrict__ C, int ldc)
{
    __shared__ float As[32 * 68];
    __shared__ float Bs[32 * 68];
    const int tid = threadIdx.x;
    const int m0 = blockIdx.y * 64, n0 = blockIdx.x * 64;
    const int tx = tid & 15, ty = tid >> 4;
    const int mt = ty * 4, nt = tx * 4;

    float acc[4][4];
#pragma unroll
    for (int i = 0; i < 4; i++)
#pragma unroll
        for (int j = 0; j < 4; j++) acc[i][j] = 0.f;

    const int kt_n = K >> 5;
    for (int kt = 0; kt < kt_n; kt++) {
        const int k0 = kt * 32;
#pragma unroll
        for (int rep = 0; rep < 2; rep++) {
            int f = tid + rep * 256;
            int row = f >> 3, kq = f & 7;
            int ar = m0 + row;
            if (idx) ar = __ldg(&idx[ar]);
            float4 av = __ldg((const float4*)(A + (size_t)ar * lda + k0 + kq * 4));
            float4 bv = __ldg((const float4*)(B + (size_t)(n0 + row) * K + k0 + kq * 4));
            As[(kq * 4 + 0) * 68 + row] = av.x;
            As[(kq * 4 + 1) * 68 + row] = av.y;
            As[(kq * 4 + 2) * 68 + row] = av.z;
            As[(kq * 4 + 3) * 68 + row] = av.w;
            Bs[(kq * 4 + 0) * 68 + row] = bv.x;
            Bs[(kq * 4 + 1) * 68 + row] = bv.y;
            Bs[(kq * 4 + 2) * 68 + row] = bv.z;
            Bs[(kq * 4 + 3) * 68 + row] = bv.w;
        }
        __syncthreads();
#pragma unroll
        for (int k = 0; k < 32; k++) {
            float4 a4 = *(const float4*)(As + k * 68 + mt);
            float4 b4 = *(const float4*)(Bs + k * 68 + nt);
            float am[4] = {a4.x, a4.y, a4.z, a4.w};
            float bn[4] = {b4.x, b4.y, b4.z, b4.w};
#pragma unroll
            for (int i = 0; i < 4; i++)
#pragma unroll
                for (int j = 0; j < 4; j++) acc[i][j] = fmaf(am[i], bn[j], acc[i][j]);
        }
        __syncthreads();
    }
    float4 b4 = __ldg((const float4*)(bias + n0 + nt));
#pragma unroll
    for (int i = 0; i < 4; i++) {
        float4 r;
        r.x = acc[i][0] + b4.x; r.y = acc[i][1] + b4.y;
        r.z = acc[i][2] + b4.z; r.w = acc[i][3] + b4.w;
        *(float4*)(C + (size_t)(m0 + mt + i) * ldc + n0 + nt) = r;
    }
}

// ---------------- GRU: 32 CTAs x 192 threads, register-resident w_hh ----------------
// Inter-CTA sync: single-level flag broadcast. CTA b's tid0 publishes step t via
// g_flags[b]=t+1 (release); every CTA's warp0 polls all 32 flags (acquire) until
// all >= t+1. No atomics, no nanosleep.
__global__ void __launch_bounds__(192) gru_kernel(
    const float* __restrict__ w_hh, const float* __restrict__ b_hh)
{
    __shared__ float sh_h[BB * HH];
    __shared__ float sh_hp[BB][24];

    const int tid = threadIdx.x;
    const int bid = blockIdx.x;
    const int row_local = tid >> 3, seg = tid & 7;
    const int gate = row_local >> 3, ii = row_local & 7;
    const int i_glob = bid * 8 + ii;
    const int wrow = gate * 256 + i_glob;

    float w[32];
    {
        const float4* ws = (const float4*)(w_hh + (size_t)wrow * 256) + seg * 8;
#pragma unroll
        for (int c = 0; c < 8; c++) {
            int cc = (c + seg) & 7;
            float4 v = __ldg(&ws[cc]);
            w[4 * c] = v.x; w[4 * c + 1] = v.y; w[4 * c + 2] = v.z; w[4 * c + 3] = v.w;
        }
    }
    const float bhh = __ldg(&b_hh[wrow]);

    const bool is_gate = (tid < 32);
    const int gb = tid >> 3, gi = tid & 7;
    const int g_i = bid * 8 + gi;

    for (int t = 0; t < TT; t++) {
        const int ping = t & 1;
        const float4* hsrc4 = (const float4*)g_h[ping];
        float4* shh4 = (float4*)sh_h;
        for (int f = tid; f < (BB * HH) / 4; f += 192)
            shh4[f] = __ldcg(&hsrc4[f]);

        float xr = 0.f, xz = 0.f, xn = 0.f;
        if (is_gate) {
            const float* xp = g_xp + ((size_t)(gb * TT + t) * 768) + g_i;
            xr = __ldg(&xp[0]); xz = __ldg(&xp[256]); xn = __ldg(&xp[512]);
        }
        __syncthreads();

        float acc0 = 0.f, acc1 = 0.f, acc2 = 0.f, acc3 = 0.f;
        const float4* hv4 = (const float4*)sh_h;
#pragma unroll
        for (int c = 0; c < 8; c++) {
            int cc = (c + seg) & 7;
            int base = seg * 8 + cc;
            float4 h0 = hv4[0 * 64 + base];
            float4 h1 = hv4[1 * 64 + base];
            float4 h2 = hv4[2 * 64 + base];
            float4 h3 = hv4[3 * 64 + base];
            float w0 = w[4 * c], w1 = w[4 * c + 1], w2 = w[4 * c + 2], w3 = w[4 * c + 3];
            acc0 = fmaf(w0, h0.x, acc0); acc1 = fmaf(w0, h1.x, acc1);
            acc2 = fmaf(w0, h2.x, acc2); acc3 = fmaf(w0, h3.x, acc3);
            acc0 = fmaf(w1, h0.y, acc0); acc1 = fmaf(w1, h1.y, acc1);
            acc2 = fmaf(w1, h2.y, acc2); acc3 = fmaf(w1, h3.y, acc3);
            acc0 = fmaf(w2, h0.z, acc0); acc1 = fmaf(w2, h1.z, acc1);
            acc2 = fmaf(w2, h2.z, acc2); acc3 = fmaf(w2, h3.z, acc3);
            acc0 = fmaf(w3, h0.w, acc0); acc1 = fmaf(w3, h1.w, acc1);
            acc2 = fmaf(w3, h2.w, acc2); acc3 = fmaf(w3, h3.w, acc3);
        }
#pragma unroll
        for (int o = 1; o < 8; o <<= 1) {
            acc0 += __shfl_xor_sync(0xffffffffu, acc0, o);
            acc1 += __shfl_xor_sync(0xffffffffu, acc1, o);
            acc2 += __shfl_xor_sync(0xffffffffu, acc2, o);
            acc3 += __shfl_xor_sync(0xffffffffu, acc3, o);
        }
        if (seg == 0) {
            sh_hp[0][row_local] = acc0 + bhh;
            sh_hp[1][row_local] = acc1 + bhh;
            sh_hp[2][row_local] = acc2 + bhh;
            sh_hp[3][row_local] = acc3 + bhh;
        }
        __syncthreads();

        if (is_gate) {
            float hr = sh_hp[gb][gi];
            float hz = sh_hp[gb][8 + gi];
            float hn = sh_hp[gb][16 + gi];
            float r = 1.f / (1.f + __expf(-(xr + hr)));
            float z = 1.f / (1.f + __expf(-(xz + hz)));
            float n = tanhf(fmaf(r, hn, xn));
            float hold = sh_h[gb * HH + g_i];
            float hnew = fmaf(z, hold - n, n);
            g_h[ping ^ 1][gb * HH + g_i] = hnew;
            g_combined[(size_t)(gb * TT + t) * 512 + g_i] = hnew;
            __threadfence();                     // order h stores before flag publish
        }
        __syncthreads();

        if (tid == 0) {
            asm volatile("st.release.gpu.global.s32 [%0], %1;"
                         :: "l"(g_flags + bid), "r"(t + 1) : "memory");
        }
        if (tid < 32) {
            int v;
            do {
                asm volatile("ld.acquire.gpu.global.s32 %0, [%1];"
                             : "=r"(v) : "l"(g_flags + tid) : "memory");
            } while (__any_sync(0xffffffffu, v <= t));
        }
        __syncthreads();
    }
}

// ---------------- attention ----------------
__global__ void __launch_bounds__(256) attn_kernel(
    const float* __restrict__ vW, const float* __restrict__ vb)
{
    __shared__ float tile[16 * 256];
    __shared__ float sc[8][512];

    const int tid = threadIdx.x;
    const int w = tid >> 5, lane = tid & 31;
    const int b = blockIdx.y, it = blockIdx.x;
    const int i = it * 8 + w;

    const float4* q4 = (const float4*)(g_q + (size_t)(b * TT + i) * HH + lane * 8);
    const float4 q0 = __ldg(q4), q1 = __ldg(q4 + 1);
    const float4* v4 = (const float4*)(vW + lane * 8);
    const float4 v0 = __ldg(v4), v1 = __ldg(v4 + 1);
    const float vbias = __ldg(vb);

    const int imax = it * 8 + 7;
    const int ntiles = (imax >> 4) + 1;

    for (int jt = 0; jt < ntiles; jt++) {
        const int j0 = jt * 16;
        float4* t4 = (float4*)tile;
#pragma unroll
        for (int rep = 0; rep < 4; rep++) {
            int f = tid + rep * 256;
            int row = f >> 6, c4 = f & 63;
            t4[f] = __ldg((const float4*)g_k + (size_t)(b * TT + j0 + row) * 64 + c4);
        }
        __syncthreads();
#pragma unroll 4
        for (int jj = 0; jj < 16; jj++) {
            int j = j0 + jj;
            if (j <= i) {
                const float4* kr = (const float4*)(tile + jj * 256) + lane * 2;
                float4 k0 = kr[0], k1 = kr[1];
                float s;
                s = v0.x * tanh_fast(q0.x + k0.x);
                s = fmaf(v0.y, tanh_fast(q0.y + k0.y), s);
                s = fmaf(v0.z, tanh_fast(q0.z + k0.z), s);
                s = fmaf(v0.w, tanh_fast(q0.w + k0.w), s);
                s = fmaf(v1.x, tanh_fast(q1.x + k1.x), s);
                s = fmaf(v1.y, tanh_fast(q1.y + k1.y), s);
                s = fmaf(v1.z, tanh_fast(q1.z + k1.z), s);
                s = fmaf(v1.w, tanh_fast(q1.w + k1.w), s);
#pragma unroll
                for (int o = 16; o > 0; o >>= 1) s += __shfl_xor_sync(0xffffffffu, s, o);
                if (lane == 0) sc[w][j] = s + vbias;
            }
        }
        __syncthreads();
    }

    float m = -1e30f;
    for (int j = lane; j <= i; j += 32) m = fmaxf(m, sc[w][j]);
#pragma unroll
    for (int o = 16; o > 0; o >>= 1) m = fmaxf(m, __shfl_xor_sync(0xffffffffu, m, o));
    float sum = 0.f;
    for (int j = lane; j <= i; j += 32) {
        float p = __expf(sc[w][j] - m);
        sc[w][j] = p;
        sum += p;
    }
#pragma unroll
    for (int o = 16; o > 0; o >>= 1) sum += __shfl_xor_sync(0xffffffffu, sum, o);
    const float inv = 1.f / sum;
    __syncthreads();

    float a0 = 0, a1 = 0, a2 = 0, a3 = 0, a4 = 0, a5 = 0, a6 = 0, a7 = 0;
    for (int jt = 0; jt < ntiles; jt++) {
        const int j0 = jt * 16;
        float4* t4 = (float4*)tile;
#pragma unroll
        for (int rep = 0; rep < 4; rep++) {
            int f = tid + rep * 256;
            int row = f >> 6, c4 = f & 63;
            t4[f] = __ldg((const float4*)g_combined + (size_t)(b * TT + j0 + row) * 128 + c4);
        }
        __syncthreads();
#pragma unroll 4
        for (int jj = 0; jj < 16; jj++) {
            int j = j0 + jj;
            if (j <= i) {
                float p = sc[w][j];
                const float4* orow = (const float4*)(tile + jj * 256) + lane * 2;
                float4 o0 = orow[0], o1 = orow[1];
                a0 = fmaf(p, o0.x, a0); a1 = fmaf(p, o0.y, a1);
                a2 = fmaf(p, o0.z, a2); a3 = fmaf(p, o0.w, a3);
                a4 = fmaf(p, o1.x, a4); a5 = fmaf(p, o1.y, a5);
                a6 = fmaf(p, o1.z, a6); a7 = fmaf(p, o1.w, a7);
            }
        }
        __syncthreads();
    }
    float* dst = g_combined + (size_t)(b * TT + i) * 512 + 256 + lane * 8;
    float4 r0 = {a0 * inv, a1 * inv, a2 * inv, a3 * inv};
    float4 r1 = {a4 * inv, a5 * inv, a6 * inv, a7 * inv};
    *(float4*)dst = r0;
    *(float4*)(dst + 4) = r1;
}

// ---------------- split-bf16 conversions ----------------
__global__ void __launch_bounds__(256) convW_kernel(const float* __restrict__ W) {
    size_t i = ((size_t)blockIdx.x * 256 + threadIdx.x) * 4;
    float4 v = __ldg((const float4*)(W + i));
    __nv_bfloat16 h[4], l[4];
    float x[4] = {v.x, v.y, v.z, v.w};
#pragma unroll
    for (int j = 0; j < 4; j++) {
        h[j] = __float2bfloat16(x[j]);
        l[j] = __float2bfloat16(x[j] - __bfloat162float(h[j]));
    }
    *(uint2*)(g_Whi + i) = *(uint2*)h;
    *(uint2*)(g_Wlo + i) = *(uint2*)l;
}

__global__ void __launch_bounds__(256) convA_kernel() {
    size_t i = ((size_t)blockIdx.x * 256 + threadIdx.x) * 4;
    float4 v = *(const float4*)(g_combined + i);
    __nv_bfloat16 h[4], l[4];
    float x[4] = {v.x, v.y, v.z, v.w};
#pragma unroll
    for (int j = 0; j < 4; j++) {
        h[j] = __float2bfloat16(x[j]);
        l[j] = __float2bfloat16(x[j] - __bfloat162float(h[j]));
    }
    *(uint2*)(g_Ahi + i) = *(uint2*)h;
    *(uint2*)(g_Alo + i) = *(uint2*)l;
}

// ---------------- FC via mma.sync HMMA ----------------
// C[2048,32000] = Ahi@Whi^T + Ahi@Wlo^T + Alo@Whi^T + bias  (split-bf16, fp32 accum).
// Effective K = 48 stages of 32; stage kc: segment kc/16 selects operand base pointers.
// CTA 128x256x32, 512 threads, 16 warps (2m x 8n), warp tile 64x32 via m16n8k16.
#define FC_BM 128
#define FC_BN 256
#define FC_BK 32
#define ROWB 80   // 64B data + 16B pad: conflict-free ldmatrix (r*5 mod 8 is a permutation)
#define FC_STAGE ((FC_BM + FC_BN) * ROWB)
#define FC_SMEM (2 * FC_STAGE)

__device__ __forceinline__ void ldmatrix_x4(uint32_t& r0, uint32_t& r1, uint32_t& r2,
                                            uint32_t& r3, uint32_t addr) {
    asm volatile("ldmatrix.sync.aligned.m8n8.x4.shared.b16 {%0,%1,%2,%3}, [%4];"
                 : "=r"(r0), "=r"(r1), "=r"(r2), "=r"(r3) : "r"(addr));
}
__device__ __forceinline__ void mma16816(float* d, const uint32_t* a, const uint32_t* b) {
    asm volatile(
        "mma.sync.aligned.m16n8k16.row.col.f32.bf16.bf16.f32 "
        "{%0,%1,%2,%3}, {%4,%5,%6,%7}, {%8,%9}, {%0,%1,%2,%3};"
        : "+f"(d[0]), "+f"(d[1]), "+f"(d[2]), "+f"(d[3])
        : "r"(a[0]), "r"(a[1]), "r"(a[2]), "r"(a[3]), "r"(b[0]), "r"(b[1]));
}
__device__ __forceinline__ void cp_async16(uint32_t dst, const void* src) {
    asm volatile("cp.async.cg.shared.global [%0], [%1], 16;" :: "r"(dst), "l"(src));
}

__global__ void __launch_bounds__(512, 1) fc_mma_kernel(
    const float* __restrict__ bias, float* __restrict__ C)
{
    extern __shared__ __align__(128) char smem[];
    const int tid = threadIdx.x;
    const int lane = tid & 31, warp = tid >> 5;
    const int wm = warp >> 3, wn = warp & 7;
    const int mBase = wm * 64, nBase = wn * 32;
    const int m0 = blockIdx.y * FC_BM, n0 = blockIdx.x * FC_BN;
    const uint32_t sm_base = smem_u32(smem);

    float acc[4][4][4];
#pragma unroll
    for (int i = 0; i < 4; i++)
#pragma unroll
        for (int j = 0; j < 4; j++)
#pragma unroll
            for (int r = 0; r < 4; r++) acc[i][j][r] = 0.f;

    auto load_stage = [&](int kc, int buf) {
        const int s = kc >> 4;
        const int kloc = (kc & 15) * 32;
        const __nv_bfloat16* Asrc = (s == 2) ? g_Alo : g_Ahi;
        const __nv_bfloat16* Bsrc = (s == 1) ? g_Wlo : g_Whi;
        const uint32_t base = sm_base + buf * FC_STAGE;
#pragma unroll
        for (int rep = 0; rep < 3; rep++) {
            int f = tid + rep * 512;
            if (f < 512) {
                int row = f >> 2, q = f & 3;
                cp_async16(base + row * ROWB + q * 16,
                           Asrc + (size_t)(m0 + row) * 512 + kloc + q * 8);
            } else {
                int g = f - 512;
                int row = g >> 2, q = g & 3;
                cp_async16(base + FC_BM * ROWB + row * ROWB + q * 16,
                           Bsrc + (size_t)(n0 + row) * 512 + kloc + q * 8);
            }
        }
        asm volatile("cp.async.commit_group;" ::: "memory");
    };

    load_stage(0, 0);

    for (int kc = 0; kc < 48; kc++) {
        const int buf = kc & 1;
        __syncthreads();
        if (kc + 1 < 48) {
            load_stage(kc + 1, buf ^ 1);
            asm volatile("cp.async.wait_group 1;" ::: "memory");
        } else {
            asm volatile("cp.async.wait_group 0;" ::: "memory");
        }
        __syncthreads();

        const uint32_t aSm = sm_base + buf * FC_STAGE;
        const uint32_t bSm = aSm + FC_BM * ROWB;
#pragma unroll
        for (int ks = 0; ks < 2; ks++) {
            const int kofsA = ks * 32 + (lane >> 4) * 16;
            const int kofsB = ks * 32 + ((lane >> 3) & 1) * 16;
            uint32_t a[4][4];
#pragma unroll
            for (int mf = 0; mf < 4; mf++) {
                int row = mBase + mf * 16 + (lane & 15);
                ldmatrix_x4(a[mf][0], a[mf][1], a[mf][2], a[mf][3],
                            aSm + row * ROWB + kofsA);
            }
            uint32_t b[4][2];
#pragma unroll
            for (int nf2 = 0; nf2 < 2; nf2++) {
                int row = nBase + nf2 * 16 + (lane & 7) + ((lane >> 4) << 3);
                uint32_t r0, r1, r2, r3;
                ldmatrix_x4(r0, r1, r2, r3, bSm + row * ROWB + kofsB);
                b[nf2 * 2 + 0][0] = r0; b[nf2 * 2 + 0][1] = r1;
                b[nf2 * 2 + 1][0] = r2; b[nf2 * 2 + 1][1] = r3;
            }
#pragma unroll
            for (int mf = 0; mf < 4; mf++)
#pragma unroll
                for (int nf = 0; nf < 4; nf++)
                    mma16816(acc[mf][nf], a[mf], b[nf]);
        }
    }

    const int mrow = m0 + mBase + (lane >> 2);
    const int ncol = n0 + nBase + (lane & 3) * 2;
    float bb[4][2];
#pragma unroll
    for (int nf = 0; nf < 4; nf++) {
        bb[nf][0] = __ldg(&bias[ncol + nf * 8]);
        bb[nf][1] = __ldg(&bias[ncol + nf * 8 + 1]);
    }
#pragma unroll
    for (int mf = 0; mf < 4; mf++) {
        float* r0p = C + (size_t)(mrow + mf * 16) * VV + ncol;
        float* r1p = C + (size_t)(mrow + mf * 16 + 8) * VV + ncol;
#pragma unroll
        for (int nf = 0; nf < 4; nf++) {
            float2 v0 = {acc[mf][nf][0] + bb[nf][0], acc[mf][nf][1] + bb[nf][1]};
            float2 v1 = {acc[mf][nf][2] + bb[nf][0], acc[mf][nf][3] + bb[nf][1]};
            *(float2*)(r0p + nf * 8) = v0;
            *(float2*)(r1p + nf * 8) = v1;
        }
    }
}

// ---------------- h_last copy ----------------
__global__ void hlast_kernel(float* __restrict__ dst) {
    int t = threadIdx.x;
    if (t < BB * HH) dst[t] = g_h[0][t];
}

// ---------------- launch ----------------
extern "C" void kernel_launch(void* const* d_in, const int* in_sizes, int n_in,
                              void* d_out, int out_size) {
    const int*   x        = (const int*)  d_in[0];
    const float* h_in     = (const float*)d_in[1];
    const float* embed_W  = (const float*)d_in[2];
    const float* gru_w_ih = (const float*)d_in[3];
    const float* gru_b_ih = (const float*)d_in[4];
    const float* gru_w_hh = (const float*)d_in[5];
    const float* gru_b_hh = (const float*)d_in[6];
    const float* attn_w_W = (const float*)d_in[7];
    const float* attn_w_b = (const float*)d_in[8];
    const float* attn_u_W = (const float*)d_in[9];
    const float* attn_u_b = (const float*)d_in[10];
    const float* attn_v_W = (const float*)d_in[11];
    const float* attn_v_b = (const float*)d_in[12];
    const float* fc_W     = (const float*)d_in[13];
    const float* fc_b     = (const float*)d_in[14];
    float* out = (float*)d_out;

    float* d_xp;       cudaGetSymbolAddress((void**)&d_xp, g_xp);
    float* d_comb;     cudaGetSymbolAddress((void**)&d_comb, g_combined);
    float* d_q;        cudaGetSymbolAddress((void**)&d_q, g_q);
    float* d_k;        cudaGetSymbolAddress((void**)&d_k, g_k);

    cudaFuncSetAttribute(fc_mma_kernel, cudaFuncAttributeMaxDynamicSharedMemorySize,
                         FC_SMEM);

    // 0. W -> bf16 hi/lo split
    convW_kernel<<<(VV * 512) / 1024, 256>>>(fc_W);

    // 1. h0 <- input h, reset GRU barrier flags
    init_kernel<<<1, 1024>>>(h_in);

    // 2. xp = embed_W[x] @ gru_w_ih^T + b_ih
    gemm_nt<<<dim3(768 / 64, BT / 64), 256>>>(embed_W, EE, x, gru_w_ih, EE,
                                              gru_b_ih, d_xp, 768);

    // 3. GRU scan (writes combined[:, :256])
    gru_kernel<<<32, 192>>>(gru_w_hh, gru_b_hh);

    // 4. q, k projections
    gemm_nt<<<dim3(HH / 64, BT / 64), 256>>>(d_comb, 512, nullptr, attn_w_W, HH,
                                             attn_w_b, d_q, HH);
    gemm_nt<<<dim3(HH / 64, BT / 64), 256>>>(d_comb, 512, nullptr, attn_u_W, HH,
                                             attn_u_b, d_k, HH);

    // 5. attention (writes combined[:, 256:])
    attn_kernel<<<dim3(TT / 8, BB), 256>>>(attn_v_W, attn_v_b);

    // 6. combined -> bf16 hi/lo split
    convA_kernel<<<(BT * 512) / 1024, 256>>>();

    // 7. logits via HMMA
    fc_mma_kernel<<<dim3(VV / FC_BN, BT / FC_BM), 512, FC_SMEM>>>(fc_b, out);

    // 8. h_last
    hlast_kernel<<<1, 1024>>>(out + (size_t)out_size - BB * HH);
}

// round 12
// speedup vs baseline: 1.7377x; 1.7377x over previous
#include <cuda_runtime.h>
#include <cuda_bf16.h>
#include <cstdint>

// Problem constants
#define BB 4
#define TT 512
#define HH 256
#define EE 256
#define VV 32000
#define BT (BB*TT)          // 2048

// ---------------- device scratch (no cudaMalloc allowed) ----------------
__device__ float g_xp[BT * 768];          // [B*T, 3H]
__device__ float g_combined[BT * 512];    // [B*T, 2H]
__device__ float g_q[BT * HH];
__device__ float g_k[BT * HH];
__device__ float g_h[BB * HH];            // h0 in, h_last out

// split-bf16 operands for the HMMA FC
__device__ __align__(256) __nv_bfloat16 g_Whi[(size_t)VV * 512];
__device__ __align__(256) __nv_bfloat16 g_Wlo[(size_t)VV * 512];
__device__ __align__(256) __nv_bfloat16 g_Ahi[(size_t)BT * 512];
__device__ __align__(256) __nv_bfloat16 g_Alo[(size_t)BT * 512];

typedef unsigned long long u64;

__device__ __forceinline__ float tanh_fast(float x) {
    float y; asm("tanh.approx.f32 %0, %1;" : "=f"(y) : "f"(x)); return y;
}
__device__ __forceinline__ uint32_t smem_u32(const void* p) {
    uint32_t a;
    asm("{ .reg .u64 t; cvta.to.shared.u64 t, %1; cvt.u32.u64 %0, t; }" : "=r"(a) : "l"(p));
    return a;
}

// ---------------- init: h0 <- input h ----------------
__global__ void init_kernel(const float* __restrict__ h_in) {
    int t = threadIdx.x;
    if (t < BB * HH) g_h[t] = h_in[t];
}

// ---------------- generic small GEMM: C[M,N] = A[M,K] @ B[N,K]^T + bias ----------------
__global__ void __launch_bounds__(256) gemm_nt(
    const float* __restrict__ A, int lda, const int* __restrict__ idx,
    const float* __restrict__ B, int K,
    const float* __restrict__ bias, float* __restrict__ C, int ldc)
{
    __shared__ float As[32 * 68];
    __shared__ float Bs[32 * 68];
    const int tid = threadIdx.x;
    const int m0 = blockIdx.y * 64, n0 = blockIdx.x * 64;
    const int tx = tid & 15, ty = tid >> 4;
    const int mt = ty * 4, nt = tx * 4;

    float acc[4][4];
#pragma unroll
    for (int i = 0; i < 4; i++)
#pragma unroll
        for (int j = 0; j < 4; j++) acc[i][j] = 0.f;

    const int kt_n = K >> 5;
    for (int kt = 0; kt < kt_n; kt++) {
        const int k0 = kt * 32;
#pragma unroll
        for (int rep = 0; rep < 2; rep++) {
            int f = tid + rep * 256;
            int row = f >> 3, kq = f & 7;
            int ar = m0 + row;
            if (idx) ar = __ldg(&idx[ar]);
            float4 av = __ldg((const float4*)(A + (size_t)ar * lda + k0 + kq * 4));
            float4 bv = __ldg((const float4*)(B + (size_t)(n0 + row) * K + k0 + kq * 4));
            As[(kq * 4 + 0) * 68 + row] = av.x;
            As[(kq * 4 + 1) * 68 + row] = av.y;
            As[(kq * 4 + 2) * 68 + row] = av.z;
            As[(kq * 4 + 3) * 68 + row] = av.w;
            Bs[(kq * 4 + 0) * 68 + row] = bv.x;
            Bs[(kq * 4 + 1) * 68 + row] = bv.y;
            Bs[(kq * 4 + 2) * 68 + row] = bv.z;
            Bs[(kq * 4 + 3) * 68 + row] = bv.w;
        }
        __syncthreads();
#pragma unroll
        for (int k = 0; k < 32; k++) {
            float4 a4 = *(const float4*)(As + k * 68 + mt);
            float4 b4 = *(const float4*)(Bs + k * 68 + nt);
            float am[4] = {a4.x, a4.y, a4.z, a4.w};
            float bn[4] = {b4.x, b4.y, b4.z, b4.w};
#pragma unroll
            for (int i = 0; i < 4; i++)
#pragma unroll
                for (int j = 0; j < 4; j++) acc[i][j] = fmaf(am[i], bn[j], acc[i][j]);
        }
        __syncthreads();
    }
    float4 b4 = __ldg((const float4*)(bias + n0 + nt));
#pragma unroll
    for (int i = 0; i < 4; i++) {
        float4 r;
        r.x = acc[i][0] + b4.x; r.y = acc[i][1] + b4.y;
        r.z = acc[i][2] + b4.z; r.w = acc[i][3] + b4.w;
        *(float4*)(C + (size_t)(m0 + mt + i) * ldc + n0 + nt) = r;
    }
}

// ---------------- GRU: 4 clusters x 8 CTAs (one cluster per batch) ----------------
// CTA (batch, rank) owns output dims [32*rank, 32*rank+32) of its batch.
// 384 threads: r_local = tid>>2 (96 rows: 3 gates x 32 dims), quar = tid&3 (64 cols).
// Weights register-resident (64/thread). h lives in own smem, written each step by
// all 8 cluster CTAs via st.shared::cluster (double-buffered); sync = barrier.cluster.
// No global-memory handshake in the recurrence at all.
__global__ void __launch_bounds__(384, 1) __cluster_dims__(8, 1, 1)
gru_kernel(const float* __restrict__ w_hh, const float* __restrict__ b_hh)
{
    __shared__ float hsm[2][4 * 68];    // quarter-strided h, double-buffered
    __shared__ float hp[96];

    const int tid = threadIdx.x;
    const int batch = blockIdx.x >> 3;
    const int rank = blockIdx.x & 7;
    const int r_local = tid >> 2;       // 0..95
    const int quar = tid & 3;
    const int gate = r_local >> 5;
    const int dl = r_local & 31;
    const int dim0 = rank * 32;
    const int wrow = gate * 256 + dim0 + dl;

    // register-resident weight slice: 64 contiguous cols of one row
    float w[64];
    {
        const float4* ws = (const float4*)(w_hh + (size_t)wrow * 256 + quar * 64);
#pragma unroll
        for (int c = 0; c < 16; c++) {
            float4 v = __ldg(&ws[c]);
            w[4 * c] = v.x; w[4 * c + 1] = v.y; w[4 * c + 2] = v.z; w[4 * c + 3] = v.w;
        }
    }
    const float bhh = __ldg(&b_hh[wrow]);

    // initial h -> hsm[0] (each CTA loads the full 256-dim h of its batch)
    for (int idx = tid; idx < HH; idx += 384)
        hsm[0][(idx >> 6) * 68 + (idx & 63)] = g_h[batch * HH + idx];

    const int myd = dim0 + (tid & 31);  // valid when tid < 32
    float xr = 0.f, xz = 0.f, xn = 0.f;
    if (tid < 32) {                      // prefetch xp for t=0
        const float* xp = g_xp + (size_t)(batch * TT) * 768 + myd;
        xr = __ldg(xp); xz = __ldg(xp + 256); xn = __ldg(xp + 512);
    }
    __syncthreads();

    for (int t = 0; t < TT; t++) {
        const int rb = t & 1, wb = rb ^ 1;
        const float4* hs4 = (const float4*)(hsm[rb] + quar * 68);

        float a0 = 0.f, a1 = 0.f, a2 = 0.f, a3 = 0.f;
#pragma unroll
        for (int c = 0; c < 16; c++) {
            float4 h = hs4[c];
            a0 = fmaf(w[4 * c + 0], h.x, a0);
            a1 = fmaf(w[4 * c + 1], h.y, a1);
            a2 = fmaf(w[4 * c + 2], h.z, a2);
            a3 = fmaf(w[4 * c + 3], h.w, a3);
        }
        float s = (a0 + a1) + (a2 + a3);
        s += __shfl_xor_sync(0xffffffffu, s, 1);
        s += __shfl_xor_sync(0xffffffffu, s, 2);
        if (quar == 0) hp[r_local] = s + bhh;
        __syncthreads();

        if (tid < 32) {
            const float hr = hp[tid], hz = hp[32 + tid], hn = hp[64 + tid];
            const float r = 1.f / (1.f + __expf(-(xr + hr)));
            const float z = 1.f / (1.f + __expf(-(xz + hz)));
            const float n = tanhf(fmaf(r, hn, xn));
            const int slot = (myd >> 6) * 68 + (myd & 63);
            const float hold = hsm[rb][slot];
            const float hnew = fmaf(z, hold - n, n);   // (1-z)*n + z*h
            g_combined[(size_t)(batch * TT + t) * 512 + myd] = hnew;

            // broadcast h_new to hsm[wb] of all 8 cluster CTAs (disjoint slots)
            const uint32_t laddr = smem_u32(&hsm[wb][slot]);
#pragma unroll
            for (int pr = 0; pr < 8; pr++) {
                uint32_t raddr;
                asm("mapa.shared::cluster.u32 %0, %1, %2;"
                    : "=r"(raddr) : "r"(laddr), "r"(pr));
                asm volatile("st.shared::cluster.f32 [%0], %1;"
                             :: "r"(raddr), "f"(hnew));
            }
            // prefetch xp for t+1
            if (t + 1 < TT) {
                const float* xp = g_xp + (size_t)(batch * TT + t + 1) * 768 + myd;
                xr = __ldg(xp); xz = __ldg(xp + 256); xn = __ldg(xp + 512);
            }
        }
        // cluster barrier: release my DSMEM stores, acquire peers'
        asm volatile("barrier.cluster.arrive.aligned;" ::: "memory");
        asm volatile("barrier.cluster.wait.aligned;" ::: "memory");
    }

    // final h (step TT lands in buffer TT&1 = 0)
    if (tid < 32)
        g_h[batch * HH + myd] = hsm[0][(myd >> 6) * 68 + (myd & 63)];
}

// ---------------- attention ----------------
__global__ void __launch_bounds__(256) attn_kernel(
    const float* __restrict__ vW, const float* __restrict__ vb)
{
    __shared__ float tile[16 * 256];
    __shared__ float sc[8][512];

    const int tid = threadIdx.x;
    const int w = tid >> 5, lane = tid & 31;
    const int b = blockIdx.y, it = blockIdx.x;
    const int i = it * 8 + w;

    const float4* q4 = (const float4*)(g_q + (size_t)(b * TT + i) * HH + lane * 8);
    const float4 q0 = __ldg(q4), q1 = __ldg(q4 + 1);
    const float4* v4 = (const float4*)(vW + lane * 8);
    const float4 v0 = __ldg(v4), v1 = __ldg(v4 + 1);
    const float vbias = __ldg(vb);

    const int imax = it * 8 + 7;
    const int ntiles = (imax >> 4) + 1;

    for (int jt = 0; jt < ntiles; jt++) {
        const int j0 = jt * 16;
        float4* t4 = (float4*)tile;
#pragma unroll
        for (int rep = 0; rep < 4; rep++) {
            int f = tid + rep * 256;
            int row = f >> 6, c4 = f & 63;
            t4[f] = __ldg((const float4*)g_k + (size_t)(b * TT + j0 + row) * 64 + c4);
        }
        __syncthreads();
#pragma unroll 4
        for (int jj = 0; jj < 16; jj++) {
            int j = j0 + jj;
            if (j <= i) {
                const float4* kr = (const float4*)(tile + jj * 256) + lane * 2;
                float4 k0 = kr[0], k1 = kr[1];
                float s;
                s = v0.x * tanh_fast(q0.x + k0.x);
                s = fmaf(v0.y, tanh_fast(q0.y + k0.y), s);
                s = fmaf(v0.z, tanh_fast(q0.z + k0.z), s);
                s = fmaf(v0.w, tanh_fast(q0.w + k0.w), s);
                s = fmaf(v1.x, tanh_fast(q1.x + k1.x), s);
                s = fmaf(v1.y, tanh_fast(q1.y + k1.y), s);
                s = fmaf(v1.z, tanh_fast(q1.z + k1.z), s);
                s = fmaf(v1.w, tanh_fast(q1.w + k1.w), s);
#pragma unroll
                for (int o = 16; o > 0; o >>= 1) s += __shfl_xor_sync(0xffffffffu, s, o);
                if (lane == 0) sc[w][j] = s + vbias;
            }
        }
        __syncthreads();
    }

    float m = -1e30f;
    for (int j = lane; j <= i; j += 32) m = fmaxf(m, sc[w][j]);
#pragma unroll
    for (int o = 16; o > 0; o >>= 1) m = fmaxf(m, __shfl_xor_sync(0xffffffffu, m, o));
    float sum = 0.f;
    for (int j = lane; j <= i; j += 32) {
        float p = __expf(sc[w][j] - m);
        sc[w][j] = p;
        sum += p;
    }
#pragma unroll
    for (int o = 16; o > 0; o >>= 1) sum += __shfl_xor_sync(0xffffffffu, sum, o);
    const float inv = 1.f / sum;
    __syncthreads();

    float a0 = 0, a1 = 0, a2 = 0, a3 = 0, a4 = 0, a5 = 0, a6 = 0, a7 = 0;
    for (int jt = 0; jt < ntiles; jt++) {
        const int j0 = jt * 16;
        float4* t4 = (float4*)tile;
#pragma unroll
        for (int rep = 0; rep < 4; rep++) {
            int f = tid + rep * 256;
            int row = f >> 6, c4 = f & 63;
            t4[f] = __ldg((const float4*)g_combined + (size_t)(b * TT + j0 + row) * 128 + c4);
        }
        __syncthreads();
#pragma unroll 4
        for (int jj = 0; jj < 16; jj++) {
            int j = j0 + jj;
            if (j <= i) {
                float p = sc[w][j];
                const float4* orow = (const float4*)(tile + jj * 256) + lane * 2;
                float4 o0 = orow[0], o1 = orow[1];
                a0 = fmaf(p, o0.x, a0); a1 = fmaf(p, o0.y, a1);
                a2 = fmaf(p, o0.z, a2); a3 = fmaf(p, o0.w, a3);
                a4 = fmaf(p, o1.x, a4); a5 = fmaf(p, o1.y, a5);
                a6 = fmaf(p, o1.z, a6); a7 = fmaf(p, o1.w, a7);
            }
        }
        __syncthreads();
    }
    float* dst = g_combined + (size_t)(b * TT + i) * 512 + 256 + lane * 8;
    float4 r0 = {a0 * inv, a1 * inv, a2 * inv, a3 * inv};
    float4 r1 = {a4 * inv, a5 * inv, a6 * inv, a7 * inv};
    *(float4*)dst = r0;
    *(float4*)(dst + 4) = r1;
}

// ---------------- split-bf16 conversions ----------------
__global__ void __launch_bounds__(256) convW_kernel(const float* __restrict__ W) {
    size_t i = ((size_t)blockIdx.x * 256 + threadIdx.x) * 4;
    float4 v = __ldg((const float4*)(W + i));
    __nv_bfloat16 h[4], l[4];
    float x[4] = {v.x, v.y, v.z, v.w};
#pragma unroll
    for (int j = 0; j < 4; j++) {
        h[j] = __float2bfloat16(x[j]);
        l[j] = __float2bfloat16(x[j] - __bfloat162float(h[j]));
    }
    *(uint2*)(g_Whi + i) = *(uint2*)h;
    *(uint2*)(g_Wlo + i) = *(uint2*)l;
}

__global__ void __launch_bounds__(256) convA_kernel() {
    size_t i = ((size_t)blockIdx.x * 256 + threadIdx.x) * 4;
    float4 v = *(const float4*)(g_combined + i);
    __nv_bfloat16 h[4], l[4];
    float x[4] = {v.x, v.y, v.z, v.w};
#pragma unroll
    for (int j = 0; j < 4; j++) {
        h[j] = __float2bfloat16(x[j]);
        l[j] = __float2bfloat16(x[j] - __bfloat162float(h[j]));
    }
    *(uint2*)(g_Ahi + i) = *(uint2*)h;
    *(uint2*)(g_Alo + i) = *(uint2*)l;
}

// ---------------- FC via mma.sync HMMA ----------------
// C[2048,32000] = Ahi@Whi^T + Ahi@Wlo^T + Alo@Whi^T + bias  (split-bf16, fp32 accum).
#define FC_BM 128
#define FC_BN 256
#define FC_BK 32
#define ROWB 80
#define FC_STAGE ((FC_BM + FC_BN) * ROWB)
#define FC_SMEM (2 * FC_STAGE)

__device__ __forceinline__ void ldmatrix_x4(uint32_t& r0, uint32_t& r1, uint32_t& r2,
                                            uint32_t& r3, uint32_t addr) {
    asm volatile("ldmatrix.sync.aligned.m8n8.x4.shared.b16 {%0,%1,%2,%3}, [%4];"
                 : "=r"(r0), "=r"(r1), "=r"(r2), "=r"(r3) : "r"(addr));
}
__device__ __forceinline__ void mma16816(float* d, const uint32_t* a, const uint32_t* b) {
    asm volatile(
        "mma.sync.aligned.m16n8k16.row.col.f32.bf16.bf16.f32 "
        "{%0,%1,%2,%3}, {%4,%5,%6,%7}, {%8,%9}, {%0,%1,%2,%3};"
        : "+f"(d[0]), "+f"(d[1]), "+f"(d[2]), "+f"(d[3])
        : "r"(a[0]), "r"(a[1]), "r"(a[2]), "r"(a[3]), "r"(b[0]), "r"(b[1]));
}
__device__ __forceinline__ void cp_async16(uint32_t dst, const void* src) {
    asm volatile("cp.async.cg.shared.global [%0], [%1], 16;" :: "r"(dst), "l"(src));
}

__global__ void __launch_bounds__(512, 1) fc_mma_kernel(
    const float* __restrict__ bias, float* __restrict__ C)
{
    extern __shared__ __align__(128) char smem[];
    const int tid = threadIdx.x;
    const int lane = tid & 31, warp = tid >> 5;
    const int wm = warp >> 3, wn = warp & 7;
    const int mBase = wm * 64, nBase = wn * 32;
    const int m0 = blockIdx.y * FC_BM, n0 = blockIdx.x * FC_BN;
    const uint32_t sm_base = smem_u32(smem);

    float acc[4][4][4];
#pragma unroll
    for (int i = 0; i < 4; i++)
#pragma unroll
        for (int j = 0; j < 4; j++)
#pragma unroll
            for (int r = 0; r < 4; r++) acc[i][j][r] = 0.f;

    auto load_stage = [&](int kc, int buf) {
        const int s = kc >> 4;
        const int kloc = (kc & 15) * 32;
        const __nv_bfloat16* Asrc = (s == 2) ? g_Alo : g_Ahi;
        const __nv_bfloat16* Bsrc = (s == 1) ? g_Wlo : g_Whi;
        const uint32_t base = sm_base + buf * FC_STAGE;
#pragma unroll
        for (int rep = 0; rep < 3; rep++) {
            int f = tid + rep * 512;
            if (f < 512) {
                int row = f >> 2, q = f & 3;
                cp_async16(base + row * ROWB + q * 16,
                           Asrc + (size_t)(m0 + row) * 512 + kloc + q * 8);
            } else {
                int g = f - 512;
                int row = g >> 2, q = g & 3;
                cp_async16(base + FC_BM * ROWB + row * ROWB + q * 16,
                           Bsrc + (size_t)(n0 + row) * 512 + kloc + q * 8);
            }
        }
        asm volatile("cp.async.commit_group;" ::: "memory");
    };

    load_stage(0, 0);

    for (int kc = 0; kc < 48; kc++) {
        const int buf = kc & 1;
        __syncthreads();
        if (kc + 1 < 48) {
            load_stage(kc + 1, buf ^ 1);
            asm volatile("cp.async.wait_group 1;" ::: "memory");
        } else {
            asm volatile("cp.async.wait_group 0;" ::: "memory");
        }
        __syncthreads();

        const uint32_t aSm = sm_base + buf * FC_STAGE;
        const uint32_t bSm = aSm + FC_BM * ROWB;
#pragma unroll
        for (int ks = 0; ks < 2; ks++) {
            const int kofsA = ks * 32 + (lane >> 4) * 16;
            const int kofsB = ks * 32 + ((lane >> 3) & 1) * 16;
            uint32_t a[4][4];
#pragma unroll
            for (int mf = 0; mf < 4; mf++) {
                int row = mBase + mf * 16 + (lane & 15);
                ldmatrix_x4(a[mf][0], a[mf][1], a[mf][2], a[mf][3],
                            aSm + row * ROWB + kofsA);
            }
            uint32_t b[4][2];
#pragma unroll
            for (int nf2 = 0; nf2 < 2; nf2++) {
                int row = nBase + nf2 * 16 + (lane & 7) + ((lane >> 4) << 3);
                uint32_t r0, r1, r2, r3;
                ldmatrix_x4(r0, r1, r2, r3, bSm + row * ROWB + kofsB);
                b[nf2 * 2 + 0][0] = r0; b[nf2 * 2 + 0][1] = r1;
                b[nf2 * 2 + 1][0] = r2; b[nf2 * 2 + 1][1] = r3;
            }
#pragma unroll
            for (int mf = 0; mf < 4; mf++)
#pragma unroll
                for (int nf = 0; nf < 4; nf++)
                    mma16816(acc[mf][nf], a[mf], b[nf]);
        }
    }

    const int mrow = m0 + mBase + (lane >> 2);
    const int ncol = n0 + nBase + (lane & 3) * 2;
    float bb[4][2];
#pragma unroll
    for (int nf = 0; nf < 4; nf++) {
        bb[nf][0] = __ldg(&bias[ncol + nf * 8]);
        bb[nf][1] = __ldg(&bias[ncol + nf * 8 + 1]);
    }
#pragma unroll
    for (int mf = 0; mf < 4; mf++) {
        float* r0p = C + (size_t)(mrow + mf * 16) * VV + ncol;
        float* r1p = C + (size_t)(mrow + mf * 16 + 8) * VV + ncol;
#pragma unroll
        for (int nf = 0; nf < 4; nf++) {
            float2 v0 = {acc[mf][nf][0] + bb[nf][0], acc[mf][nf][1] + bb[nf][1]};
            float2 v1 = {acc[mf][nf][2] + bb[nf][0], acc[mf][nf][3] + bb[nf][1]};
            *(float2*)(r0p + nf * 8) = v0;
            *(float2*)(r1p + nf * 8) = v1;
        }
    }
}

// ---------------- h_last copy ----------------
__global__ void hlast_kernel(float* __restrict__ dst) {
    int t = threadIdx.x;
    if (t < BB * HH) dst[t] = g_h[t];
}

// ---------------- launch ----------------
extern "C" void kernel_launch(void* const* d_in, const int* in_sizes, int n_in,
                              void* d_out, int out_size) {
    const int*   x        = (const int*)  d_in[0];
    const float* h_in     = (const float*)d_in[1];
    const float* embed_W  = (const float*)d_in[2];
    const float* gru_w_ih = (const float*)d_in[3];
    const float* gru_b_ih = (const float*)d_in[4];
    const float* gru_w_hh = (const float*)d_in[5];
    const float* gru_b_hh = (const float*)d_in[6];
    const float* attn_w_W = (const float*)d_in[7];
    const float* attn_w_b = (const float*)d_in[8];
    const float* attn_u_W = (const float*)d_in[9];
    const float* attn_u_b = (const float*)d_in[10];
    const float* attn_v_W = (const float*)d_in[11];
    const float* attn_v_b = (const float*)d_in[12];
    const float* fc_W     = (const float*)d_in[13];
    const float* fc_b     = (const float*)d_in[14];
    float* out = (float*)d_out;

    float* d_xp;       cudaGetSymbolAddress((void**)&d_xp, g_xp);
    float* d_comb;     cudaGetSymbolAddress((void**)&d_comb, g_combined);
    float* d_q;        cudaGetSymbolAddress((void**)&d_q, g_q);
    float* d_k;        cudaGetSymbolAddress((void**)&d_k, g_k);

    cudaFuncSetAttribute(fc_mma_kernel, cudaFuncAttributeMaxDynamicSharedMemorySize,
                         FC_SMEM);

    // 0. W -> bf16 hi/lo split
    convW_kernel<<<(VV * 512) / 1024, 256>>>(fc_W);

    // 1. h0 <- input h
    init_kernel<<<1, 1024>>>(h_in);

    // 2. xp = embed_W[x] @ gru_w_ih^T + b_ih
    gemm_nt<<<dim3(768 / 64, BT / 64), 256>>>(embed_W, EE, x, gru_w_ih, EE,
                                              gru_b_ih, d_xp, 768);

    // 3. GRU scan: 4 clusters of 8 CTAs (writes combined[:, :256])
    gru_kernel<<<32, 384>>>(gru_w_hh, gru_b_hh);

    // 4. q, k projections
    gemm_nt<<<dim3(HH / 64, BT / 64), 256>>>(d_comb, 512, nullptr, attn_w_W, HH,
                                             attn_w_b, d_q, HH);
    gemm_nt<<<dim3(HH / 64, BT / 64), 256>>>(d_comb, 512, nullptr, attn_u_W, HH,
                                             attn_u_b, d_k, HH);

    // 5. attention (writes combined[:, 256:])
    attn_kernel<<<dim3(TT / 8, BB), 256>>>(attn_v_W, attn_v_b);

    // 6. combined -> bf16 hi/lo split
    convA_kernel<<<(BT * 512) / 1024, 256>>>();

    // 7. logits via HMMA
    fc_mma_kernel<<<dim3(VV / FC_BN, BT / FC_BM), 512, FC_SMEM>>>(fc_b, out);

    // 8. h_last
    hlast_kernel<<<1, 1024>>>(out + (size_t)out_size - BB * HH);
}

// round 13
// speedup vs baseline: 1.9095x; 1.0988x over previous
#include <cuda_runtime.h>
#include <cuda_bf16.h>
#include <cstdint>

// Problem constants
#define BB 4
#define TT 512
#define HH 256
#define EE 256
#define VV 32000
#define BT (BB*TT)          // 2048

// ---------------- device scratch (no cudaMalloc allowed) ----------------
__device__ float g_xp[BT * 768];          // [B*T, 3H]
__device__ float g_combined[BT * 512];    // [B*T, 2H]
__device__ float g_q[BT * HH];
__device__ float g_k[BT * HH];
__device__ float g_h[BB * HH];            // h0 in, h_last out

// split-bf16 operands for the HMMA FC
__device__ __align__(256) __nv_bfloat16 g_Whi[(size_t)VV * 512];
__device__ __align__(256) __nv_bfloat16 g_Wlo[(size_t)VV * 512];
__device__ __align__(256) __nv_bfloat16 g_Ahi[(size_t)BT * 512];
__device__ __align__(256) __nv_bfloat16 g_Alo[(size_t)BT * 512];

typedef unsigned long long u64;

__device__ __forceinline__ float tanh_fast(float x) {
    float y; asm("tanh.approx.f32 %0, %1;" : "=f"(y) : "f"(x)); return y;
}
__device__ __forceinline__ uint32_t smem_u32(const void* p) {
    uint32_t a;
    asm("{ .reg .u64 t; cvta.to.shared.u64 t, %1; cvt.u32.u64 %0, t; }" : "=r"(a) : "l"(p));
    return a;
}
__device__ __forceinline__ u64 pack2(float lo, float hi) {
    u64 r; asm("mov.b64 %0, {%1,%2};" : "=l"(r) : "f"(lo), "f"(hi)); return r;
}
__device__ __forceinline__ void unpack2(u64 v, float& lo, float& hi) {
    asm("mov.b64 {%0,%1}, %2;" : "=f"(lo), "=f"(hi) : "l"(v));
}
__device__ __forceinline__ u64 ffma2(u64 a, u64 b, u64 c) {
    u64 d; asm("fma.rn.f32x2 %0, %1, %2, %3;" : "=l"(d) : "l"(a), "l"(b), "l"(c)); return d;
}

// ---------------- init: h0 <- input h ----------------
__global__ void init_kernel(const float* __restrict__ h_in) {
    int t = threadIdx.x;
    if (t < BB * HH) g_h[t] = h_in[t];
}

// ---------------- generic small GEMM: C[M,N] = A[M,K] @ B[N,K]^T + bias ----------------
__global__ void __launch_bounds__(256) gemm_nt(
    const float* __restrict__ A, int lda, const int* __restrict__ idx,
    const float* __restrict__ B, int K,
    const float* __restrict__ bias, float* __restrict__ C, int ldc)
{
    __shared__ float As[32 * 68];
    __shared__ float Bs[32 * 68];
    const int tid = threadIdx.x;
    const int m0 = blockIdx.y * 64, n0 = blockIdx.x * 64;
    const int tx = tid & 15, ty = tid >> 4;
    const int mt = ty * 4, nt = tx * 4;

    float acc[4][4];
#pragma unroll
    for (int i = 0; i < 4; i++)
#pragma unroll
        for (int j = 0; j < 4; j++) acc[i][j] = 0.f;

    const int kt_n = K >> 5;
    for (int kt = 0; kt < kt_n; kt++) {
        const int k0 = kt * 32;
#pragma unroll
        for (int rep = 0; rep < 2; rep++) {
            int f = tid + rep * 256;
            int row = f >> 3, kq = f & 7;
            int ar = m0 + row;
            if (idx) ar = __ldg(&idx[ar]);
            float4 av = __ldg((const float4*)(A + (size_t)ar * lda + k0 + kq * 4));
            float4 bv = __ldg((const float4*)(B + (size_t)(n0 + row) * K + k0 + kq * 4));
            As[(kq * 4 + 0) * 68 + row] = av.x;
            As[(kq * 4 + 1) * 68 + row] = av.y;
            As[(kq * 4 + 2) * 68 + row] = av.z;
            As[(kq * 4 + 3) * 68 + row] = av.w;
            Bs[(kq * 4 + 0) * 68 + row] = bv.x;
            Bs[(kq * 4 + 1) * 68 + row] = bv.y;
            Bs[(kq * 4 + 2) * 68 + row] = bv.z;
            Bs[(kq * 4 + 3) * 68 + row] = bv.w;
        }
        __syncthreads();
#pragma unroll
        for (int k = 0; k < 32; k++) {
            float4 a4 = *(const float4*)(As + k * 68 + mt);
            float4 b4 = *(const float4*)(Bs + k * 68 + nt);
            float am[4] = {a4.x, a4.y, a4.z, a4.w};
            float bn[4] = {b4.x, b4.y, b4.z, b4.w};
#pragma unroll
            for (int i = 0; i < 4; i++)
#pragma unroll
                for (int j = 0; j < 4; j++) acc[i][j] = fmaf(am[i], bn[j], acc[i][j]);
        }
        __syncthreads();
    }
    float4 b4 = __ldg((const float4*)(bias + n0 + nt));
#pragma unroll
    for (int i = 0; i < 4; i++) {
        float4 r;
        r.x = acc[i][0] + b4.x; r.y = acc[i][1] + b4.y;
        r.z = acc[i][2] + b4.z; r.w = acc[i][3] + b4.w;
        *(float4*)(C + (size_t)(m0 + mt + i) * ldc + n0 + nt) = r;
    }
}

// ---------------- GRU: 4 clusters x 8 CTAs (one cluster per batch) ----------------
// Same structure as R11 (WIN) but matvec uses packed f32x2 FFMA2 (half the fma
// instructions) and the n-gate uses tanh.approx.
__global__ void __launch_bounds__(384, 1) __cluster_dims__(8, 1, 1)
gru_kernel(const float* __restrict__ w_hh, const float* __restrict__ b_hh)
{
    __shared__ __align__(16) float hsm[2][4 * 68];    // quarter-strided h, double-buffered
    __shared__ float hp[96];

    const int tid = threadIdx.x;
    const int batch = blockIdx.x >> 3;
    const int rank = blockIdx.x & 7;
    const int r_local = tid >> 2;       // 0..95
    const int quar = tid & 3;
    const int gate = r_local >> 5;
    const int dl = r_local & 31;
    const int dim0 = rank * 32;
    const int wrow = gate * 256 + dim0 + dl;

    // register-resident weight slice: 64 contiguous cols of one row, packed f32x2
    u64 w2[32];
    {
        const float4* ws = (const float4*)(w_hh + (size_t)wrow * 256 + quar * 64);
#pragma unroll
        for (int c = 0; c < 16; c++) {
            float4 v = __ldg(&ws[c]);
            w2[2 * c]     = pack2(v.x, v.y);
            w2[2 * c + 1] = pack2(v.z, v.w);
        }
    }
    const float bhh = __ldg(&b_hh[wrow]);

    // initial h -> hsm[0]
    for (int idx = tid; idx < HH; idx += 384)
        hsm[0][(idx >> 6) * 68 + (idx & 63)] = g_h[batch * HH + idx];

    const int myd = dim0 + (tid & 31);  // valid when tid < 32
    float xr = 0.f, xz = 0.f, xn = 0.f;
    if (tid < 32) {                      // prefetch xp for t=0
        const float* xp = g_xp + (size_t)(batch * TT) * 768 + myd;
        xr = __ldg(xp); xz = __ldg(xp + 256); xn = __ldg(xp + 512);
    }
    __syncthreads();

    for (int t = 0; t < TT; t++) {
        const int rb = t & 1, wb = rb ^ 1;
        const ulonglong2* hs2 = (const ulonglong2*)(hsm[rb] + quar * 68);

        // 4 independent ffma2 chains of depth 8
        u64 acc0 = 0ull, acc1 = 0ull, acc2 = 0ull, acc3 = 0ull;
#pragma unroll
        for (int c = 0; c < 16; c += 2) {
            ulonglong2 h0 = hs2[c];
            ulonglong2 h1 = hs2[c + 1];
            acc0 = ffma2(w2[2 * c + 0], h0.x, acc0);
            acc1 = ffma2(w2[2 * c + 1], h0.y, acc1);
            acc2 = ffma2(w2[2 * c + 2], h1.x, acc2);
            acc3 = ffma2(w2[2 * c + 3], h1.y, acc3);
        }
        float l0, u0, l1, u1, l2, u2, l3, u3;
        unpack2(acc0, l0, u0); unpack2(acc1, l1, u1);
        unpack2(acc2, l2, u2); unpack2(acc3, l3, u3);
        float s = ((l0 + u0) + (l1 + u1)) + ((l2 + u2) + (l3 + u3));
        s += __shfl_xor_sync(0xffffffffu, s, 1);
        s += __shfl_xor_sync(0xffffffffu, s, 2);
        if (quar == 0) hp[r_local] = s + bhh;
        __syncthreads();

        if (tid < 32) {
            const float hr = hp[tid], hz = hp[32 + tid], hn = hp[64 + tid];
            const float r = 1.f / (1.f + __expf(-(xr + hr)));
            const float z = 1.f / (1.f + __expf(-(xz + hz)));
            const float n = tanh_fast(fmaf(r, hn, xn));
            const int slot = (myd >> 6) * 68 + (myd & 63);
            const float hold = hsm[rb][slot];
            const float hnew = fmaf(z, hold - n, n);   // (1-z)*n + z*h
            g_combined[(size_t)(batch * TT + t) * 512 + myd] = hnew;

            // broadcast h_new to hsm[wb] of all 8 cluster CTAs (disjoint slots)
            const uint32_t laddr = smem_u32(&hsm[wb][slot]);
#pragma unroll
            for (int pr = 0; pr < 8; pr++) {
                uint32_t raddr;
                asm("mapa.shared::cluster.u32 %0, %1, %2;"
                    : "=r"(raddr) : "r"(laddr), "r"(pr));
                asm volatile("st.shared::cluster.f32 [%0], %1;"
                             :: "r"(raddr), "f"(hnew));
            }
            // prefetch xp for t+1
            if (t + 1 < TT) {
                const float* xp = g_xp + (size_t)(batch * TT + t + 1) * 768 + myd;
                xr = __ldg(xp); xz = __ldg(xp + 256); xn = __ldg(xp + 512);
            }
        }
        // cluster barrier: release my DSMEM stores, acquire peers'
        asm volatile("barrier.cluster.arrive.aligned;" ::: "memory");
        asm volatile("barrier.cluster.wait.aligned;" ::: "memory");
    }

    // final h (step TT lands in buffer TT&1 = 0)
    if (tid < 32)
        g_h[batch * HH + myd] = hsm[0][(myd >> 6) * 68 + (myd & 63)];
}

// ---------------- attention ----------------
__global__ void __launch_bounds__(256) attn_kernel(
    const float* __restrict__ vW, const float* __restrict__ vb)
{
    __shared__ float tile[16 * 256];
    __shared__ float sc[8][512];

    const int tid = threadIdx.x;
    const int w = tid >> 5, lane = tid & 31;
    const int b = blockIdx.y, it = blockIdx.x;
    const int i = it * 8 + w;

    const float4* q4 = (const float4*)(g_q + (size_t)(b * TT + i) * HH + lane * 8);
    const float4 q0 = __ldg(q4), q1 = __ldg(q4 + 1);
    const float4* v4 = (const float4*)(vW + lane * 8);
    const float4 v0 = __ldg(v4), v1 = __ldg(v4 + 1);
    const float vbias = __ldg(vb);

    const int imax = it * 8 + 7;
    const int ntiles = (imax >> 4) + 1;

    for (int jt = 0; jt < ntiles; jt++) {
        const int j0 = jt * 16;
        float4* t4 = (float4*)tile;
#pragma unroll
        for (int rep = 0; rep < 4; rep++) {
            int f = tid + rep * 256;
            int row = f >> 6, c4 = f & 63;
            t4[f] = __ldg((const float4*)g_k + (size_t)(b * TT + j0 + row) * 64 + c4);
        }
        __syncthreads();
#pragma unroll 4
        for (int jj = 0; jj < 16; jj++) {
            int j = j0 + jj;
            if (j <= i) {
                const float4* kr = (const float4*)(tile + jj * 256) + lane * 2;
                float4 k0 = kr[0], k1 = kr[1];
                float s;
                s = v0.x * tanh_fast(q0.x + k0.x);
                s = fmaf(v0.y, tanh_fast(q0.y + k0.y), s);
                s = fmaf(v0.z, tanh_fast(q0.z + k0.z), s);
                s = fmaf(v0.w, tanh_fast(q0.w + k0.w), s);
                s = fmaf(v1.x, tanh_fast(q1.x + k1.x), s);
                s = fmaf(v1.y, tanh_fast(q1.y + k1.y), s);
                s = fmaf(v1.z, tanh_fast(q1.z + k1.z), s);
                s = fmaf(v1.w, tanh_fast(q1.w + k1.w), s);
#pragma unroll
                for (int o = 16; o > 0; o >>= 1) s += __shfl_xor_sync(0xffffffffu, s, o);
                if (lane == 0) sc[w][j] = s + vbias;
            }
        }
        __syncthreads();
    }

    float m = -1e30f;
    for (int j = lane; j <= i; j += 32) m = fmaxf(m, sc[w][j]);
#pragma unroll
    for (int o = 16; o > 0; o >>= 1) m = fmaxf(m, __shfl_xor_sync(0xffffffffu, m, o));
    float sum = 0.f;
    for (int j = lane; j <= i; j += 32) {
        float p = __expf(sc[w][j] - m);
        sc[w][j] = p;
        sum += p;
    }
#pragma unroll
    for (int o = 16; o > 0; o >>= 1) sum += __shfl_xor_sync(0xffffffffu, sum, o);
    const float inv = 1.f / sum;
    __syncthreads();

    float a0 = 0, a1 = 0, a2 = 0, a3 = 0, a4 = 0, a5 = 0, a6 = 0, a7 = 0;
    for (int jt = 0; jt < ntiles; jt++) {
        const int j0 = jt * 16;
        float4* t4 = (float4*)tile;
#pragma unroll
        for (int rep = 0; rep < 4; rep++) {
            int f = tid + rep * 256;
            int row = f >> 6, c4 = f & 63;
            t4[f] = __ldg((const float4*)g_combined + (size_t)(b * TT + j0 + row) * 128 + c4);
        }
        __syncthreads();
#pragma unroll 4
        for (int jj = 0; jj < 16; jj++) {
            int j = j0 + jj;
            if (j <= i) {
                float p = sc[w][j];
                const float4* orow = (const float4*)(tile + jj * 256) + lane * 2;
                float4 o0 = orow[0], o1 = orow[1];
                a0 = fmaf(p, o0.x, a0); a1 = fmaf(p, o0.y, a1);
                a2 = fmaf(p, o0.z, a2); a3 = fmaf(p, o0.w, a3);
                a4 = fmaf(p, o1.x, a4); a5 = fmaf(p, o1.y, a5);
                a6 = fmaf(p, o1.z, a6); a7 = fmaf(p, o1.w, a7);
            }
        }
        __syncthreads();
    }
    float* dst = g_combined + (size_t)(b * TT + i) * 512 + 256 + lane * 8;
    float4 r0 = {a0 * inv, a1 * inv, a2 * inv, a3 * inv};
    float4 r1 = {a4 * inv, a5 * inv, a6 * inv, a7 * inv};
    *(float4*)dst = r0;
    *(float4*)(dst + 4) = r1;
}

// ---------------- split-bf16 conversions ----------------
__global__ void __launch_bounds__(256) convW_kernel(const float* __restrict__ W) {
    size_t i = ((size_t)blockIdx.x * 256 + threadIdx.x) * 4;
    float4 v = __ldg((const float4*)(W + i));
    __nv_bfloat16 h[4], l[4];
    float x[4] = {v.x, v.y, v.z, v.w};
#pragma unroll
    for (int j = 0; j < 4; j++) {
        h[j] = __float2bfloat16(x[j]);
        l[j] = __float2bfloat16(x[j] - __bfloat162float(h[j]));
    }
    *(uint2*)(g_Whi + i) = *(uint2*)h;
    *(uint2*)(g_Wlo + i) = *(uint2*)l;
}

__global__ void __launch_bounds__(256) convA_kernel() {
    size_t i = ((size_t)blockIdx.x * 256 + threadIdx.x) * 4;
    float4 v = *(const float4*)(g_combined + i);
    __nv_bfloat16 h[4], l[4];
    float x[4] = {v.x, v.y, v.z, v.w};
#pragma unroll
    for (int j = 0; j < 4; j++) {
        h[j] = __float2bfloat16(x[j]);
        l[j] = __float2bfloat16(x[j] - __bfloat162float(h[j]));
    }
    *(uint2*)(g_Ahi + i) = *(uint2*)h;
    *(uint2*)(g_Alo + i) = *(uint2*)l;
}

// ---------------- FC via mma.sync HMMA ----------------
// C[2048,32000] = Ahi@Whi^T + Ahi@Wlo^T + Alo@Whi^T + bias  (split-bf16, fp32 accum).
// CTA 128x128x32, 256 threads, 8 warps (2m x 4n), warp tile 64x32, 2 CTAs/SM.
#define FC_BM 128
#define FC_BN 128
#define ROWB 80
#define FC_STAGE ((FC_BM + FC_BN) * ROWB)      // 20480
#define FC_SMEM (2 * FC_STAGE)                 // 40960

__device__ __forceinline__ void ldmatrix_x4(uint32_t& r0, uint32_t& r1, uint32_t& r2,
                                            uint32_t& r3, uint32_t addr) {
    asm volatile("ldmatrix.sync.aligned.m8n8.x4.shared.b16 {%0,%1,%2,%3}, [%4];"
                 : "=r"(r0), "=r"(r1), "=r"(r2), "=r"(r3) : "r"(addr));
}
__device__ __forceinline__ void mma16816(float* d, const uint32_t* a, const uint32_t* b) {
    asm volatile(
        "mma.sync.aligned.m16n8k16.row.col.f32.bf16.bf16.f32 "
        "{%0,%1,%2,%3}, {%4,%5,%6,%7}, {%8,%9}, {%0,%1,%2,%3};"
        : "+f"(d[0]), "+f"(d[1]), "+f"(d[2]), "+f"(d[3])
        : "r"(a[0]), "r"(a[1]), "r"(a[2]), "r"(a[3]), "r"(b[0]), "r"(b[1]));
}
__device__ __forceinline__ void cp_async16(uint32_t dst, const void* src) {
    asm volatile("cp.async.cg.shared.global [%0], [%1], 16;" :: "r"(dst), "l"(src));
}

__global__ void __launch_bounds__(256, 2) fc_mma_kernel(
    const float* __restrict__ bias, float* __restrict__ C)
{
    extern __shared__ __align__(128) char smem[];
    const int tid = threadIdx.x;
    const int lane = tid & 31, warp = tid >> 5;
    const int wm = warp >> 2, wn = warp & 3;
    const int mBase = wm * 64, nBase = wn * 32;
    const int m0 = blockIdx.y * FC_BM, n0 = blockIdx.x * FC_BN;
    const uint32_t sm_base = smem_u32(smem);

    float acc[4][4][4];
#pragma unroll
    for (int i = 0; i < 4; i++)
#pragma unroll
        for (int j = 0; j < 4; j++)
#pragma unroll
            for (int r = 0; r < 4; r++) acc[i][j][r] = 0.f;

    auto load_stage = [&](int kc, int buf) {
        const int s = kc >> 4;
        const int kloc = (kc & 15) * 32;
        const __nv_bfloat16* Asrc = (s == 2) ? g_Alo : g_Ahi;
        const __nv_bfloat16* Bsrc = (s == 1) ? g_Wlo : g_Whi;
        const uint32_t base = sm_base + buf * FC_STAGE;
#pragma unroll
        for (int rep = 0; rep < 4; rep++) {
            int f = tid + rep * 256;
            if (f < 512) {
                int row = f >> 2, q = f & 3;
                cp_async16(base + row * ROWB + q * 16,
                           Asrc + (size_t)(m0 + row) * 512 + kloc + q * 8);
            } else {
                int g = f - 512;
                int row = g >> 2, q = g & 3;
                cp_async16(base + FC_BM * ROWB + row * ROWB + q * 16,
                           Bsrc + (size_t)(n0 + row) * 512 + kloc + q * 8);
            }
        }
        asm volatile("cp.async.commit_group;" ::: "memory");
    };

    load_stage(0, 0);

    for (int kc = 0; kc < 48; kc++) {
        const int buf = kc & 1;
        __syncthreads();
        if (kc + 1 < 48) {
            load_stage(kc + 1, buf ^ 1);
            asm volatile("cp.async.wait_group 1;" ::: "memory");
        } else {
            asm volatile("cp.async.wait_group 0;" ::: "memory");
        }
        __syncthreads();

        const uint32_t aSm = sm_base + buf * FC_STAGE;
        const uint32_t bSm = aSm + FC_BM * ROWB;
#pragma unroll
        for (int ks = 0; ks < 2; ks++) {
            const int kofsA = ks * 32 + (lane >> 4) * 16;
            const int kofsB = ks * 32 + ((lane >> 3) & 1) * 16;
            uint32_t a[4][4];
#pragma unroll
            for (int mf = 0; mf < 4; mf++) {
                int row = mBase + mf * 16 + (lane & 15);
                ldmatrix_x4(a[mf][0], a[mf][1], a[mf][2], a[mf][3],
                            aSm + row * ROWB + kofsA);
            }
            uint32_t b[4][2];
#pragma unroll
            for (int nf2 = 0; nf2 < 2; nf2++) {
                int row = nBase + nf2 * 16 + (lane & 7) + ((lane >> 4) << 3);
                uint32_t r0, r1, r2, r3;
                ldmatrix_x4(r0, r1, r2, r3, bSm + row * ROWB + kofsB);
                b[nf2 * 2 + 0][0] = r0; b[nf2 * 2 + 0][1] = r1;
                b[nf2 * 2 + 1][0] = r2; b[nf2 * 2 + 1][1] = r3;
            }
#pragma unroll
            for (int mf = 0; mf < 4; mf++)
#pragma unroll
                for (int nf = 0; nf < 4; nf++)
                    mma16816(acc[mf][nf], a[mf], b[nf]);
        }
    }

    const int mrow = m0 + mBase + (lane >> 2);
    const int ncol = n0 + nBase + (lane & 3) * 2;
    float bb[4][2];
#pragma unroll
    for (int nf = 0; nf < 4; nf++) {
        bb[nf][0] = __ldg(&bias[ncol + nf * 8]);
        bb[nf][1] = __ldg(&bias[ncol + nf * 8 + 1]);
    }
#pragma unroll
    for (int mf = 0; mf < 4; mf++) {
        float* r0p = C + (size_t)(mrow + mf * 16) * VV + ncol;
        float* r1p = C + (size_t)(mrow + mf * 16 + 8) * VV + ncol;
#pragma unroll
        for (int nf = 0; nf < 4; nf++) {
            float2 v0 = {acc[mf][nf][0] + bb[nf][0], acc[mf][nf][1] + bb[nf][1]};
            float2 v1 = {acc[mf][nf][2] + bb[nf][0], acc[mf][nf][3] + bb[nf][1]};
            *(float2*)(r0p + nf * 8) = v0;
            *(float2*)(r1p + nf * 8) = v1;
        }
    }
}

// ---------------- h_last copy ----------------
__global__ void hlast_kernel(float* __restrict__ dst) {
    int t = threadIdx.x;
    if (t < BB * HH) dst[t] = g_h[t];
}

// ---------------- launch ----------------
extern "C" void kernel_launch(void* const* d_in, const int* in_sizes, int n_in,
                              void* d_out, int out_size) {
    const int*   x        = (const int*)  d_in[0];
    const float* h_in     = (const float*)d_in[1];
    const float* embed_W  = (const float*)d_in[2];
    const float* gru_w_ih = (const float*)d_in[3];
    const float* gru_b_ih = (const float*)d_in[4];
    const float* gru_w_hh = (const float*)d_in[5];
    const float* gru_b_hh = (const float*)d_in[6];
    const float* attn_w_W = (const float*)d_in[7];
    const float* attn_w_b = (const float*)d_in[8];
    const float* attn_u_W = (const float*)d_in[9];
    const float* attn_u_b = (const float*)d_in[10];
    const float* attn_v_W = (const float*)d_in[11];
    const float* attn_v_b = (const float*)d_in[12];
    const float* fc_W     = (const float*)d_in[13];
    const float* fc_b     = (const float*)d_in[14];
    float* out = (float*)d_out;

    float* d_xp;       cudaGetSymbolAddress((void**)&d_xp, g_xp);
    float* d_comb;     cudaGetSymbolAddress((void**)&d_comb, g_combined);
    float* d_q;        cudaGetSymbolAddress((void**)&d_q, g_q);
    float* d_k;        cudaGetSymbolAddress((void**)&d_k, g_k);

    cudaFuncSetAttribute(fc_mma_kernel, cudaFuncAttributeMaxDynamicSharedMemorySize,
                         FC_SMEM);

    // 0. W -> bf16 hi/lo split
    convW_kernel<<<(VV * 512) / 1024, 256>>>(fc_W);

    // 1. h0 <- input h
    init_kernel<<<1, 1024>>>(h_in);

    // 2. xp = embed_W[x] @ gru_w_ih^T + b_ih
    gemm_nt<<<dim3(768 / 64, BT / 64), 256>>>(embed_W, EE, x, gru_w_ih, EE,
                                              gru_b_ih, d_xp, 768);

    // 3. GRU scan: 4 clusters of 8 CTAs (writes combined[:, :256])
    gru_kernel<<<32, 384>>>(gru_w_hh, gru_b_hh);

    // 4. q, k projections
    gemm_nt<<<dim3(HH / 64, BT / 64), 256>>>(d_comb, 512, nullptr, attn_w_W, HH,
                                             attn_w_b, d_q, HH);
    gemm_nt<<<dim3(HH / 64, BT / 64), 256>>>(d_comb, 512, nullptr, attn_u_W, HH,
                                             attn_u_b, d_k, HH);

    // 5. attention (writes combined[:, 256:])
    attn_kernel<<<dim3(TT / 8, BB), 256>>>(attn_v_W, attn_v_b);

    // 6. combined -> bf16 hi/lo split
    convA_kernel<<<(BT * 512) / 1024, 256>>>();

    // 7. logits via HMMA (128x128 tiles, 2 CTAs/SM)
    fc_mma_kernel<<<dim3(VV / FC_BN, BT / FC_BM), 256, FC_SMEM>>>(fc_b, out);

    // 8. h_last
    hlast_kernel<<<1, 1024>>>(out + (size_t)out_size - BB * HH);
}

// round 15
// speedup vs baseline: 2.0902x; 1.0947x over previous
#include <cuda_runtime.h>
#include <cuda_bf16.h>
#include <cstdint>

// Problem constants
#define BB 4
#define TT 512
#define HH 256
#define EE 256
#define VV 32000
#define BT (BB*TT)          // 2048

// ---------------- device scratch (no cudaMalloc allowed) ----------------
__device__ float g_xp[BT * 768];          // [B*T, 3H]
__device__ float g_combined[BT * 512];    // [B*T, 2H]
__device__ float g_q[BT * HH];
__device__ float g_k[BT * HH];
__device__ float g_h[BB * HH];            // h0 in, h_last out

// split-bf16 operands for the HMMA FC
__device__ __align__(256) __nv_bfloat16 g_Whi[(size_t)VV * 512];
__device__ __align__(256) __nv_bfloat16 g_Wlo[(size_t)VV * 512];
__device__ __align__(256) __nv_bfloat16 g_Ahi[(size_t)BT * 512];
__device__ __align__(256) __nv_bfloat16 g_Alo[(size_t)BT * 512];

typedef unsigned long long u64;

__device__ __forceinline__ float tanh_fast(float x) {
    float y; asm("tanh.approx.f32 %0, %1;" : "=f"(y) : "f"(x)); return y;
}
__device__ __forceinline__ uint32_t smem_u32(const void* p) {
    uint32_t a;
    asm("{ .reg .u64 t; cvta.to.shared.u64 t, %1; cvt.u32.u64 %0, t; }" : "=r"(a) : "l"(p));
    return a;
}
__device__ __forceinline__ u64 pack2(float lo, float hi) {
    u64 r; asm("mov.b64 %0, {%1,%2};" : "=l"(r) : "f"(lo), "f"(hi)); return r;
}
__device__ __forceinline__ void unpack2(u64 v, float& lo, float& hi) {
    asm("mov.b64 {%0,%1}, %2;" : "=f"(lo), "=f"(hi) : "l"(v));
}
__device__ __forceinline__ u64 ffma2(u64 a, u64 b, u64 c) {
    u64 d; asm("fma.rn.f32x2 %0, %1, %2, %3;" : "=l"(d) : "l"(a), "l"(b), "l"(c)); return d;
}

// ---------------- init: h0 <- input h ----------------
__global__ void init_kernel(const float* __restrict__ h_in) {
    int t = threadIdx.x;
    if (t < BB * HH) g_h[t] = h_in[t];
}

// ---------------- generic small GEMM: C[M,N] = A[M,K] @ B[N,K]^T + bias ----------------
__global__ void __launch_bounds__(256) gemm_nt(
    const float* __restrict__ A, int lda, const int* __restrict__ idx,
    const float* __restrict__ B, int K,
    const float* __restrict__ bias, float* __restrict__ C, int ldc)
{
    __shared__ float As[32 * 68];
    __shared__ float Bs[32 * 68];
    const int tid = threadIdx.x;
    const int m0 = blockIdx.y * 64, n0 = blockIdx.x * 64;
    const int tx = tid & 15, ty = tid >> 4;
    const int mt = ty * 4, nt = tx * 4;

    float acc[4][4];
#pragma unroll
    for (int i = 0; i < 4; i++)
#pragma unroll
        for (int j = 0; j < 4; j++) acc[i][j] = 0.f;

    const int kt_n = K >> 5;
    for (int kt = 0; kt < kt_n; kt++) {
        const int k0 = kt * 32;
#pragma unroll
        for (int rep = 0; rep < 2; rep++) {
            int f = tid + rep * 256;
            int row = f >> 3, kq = f & 7;
            int ar = m0 + row;
            if (idx) ar = __ldg(&idx[ar]);
            float4 av = __ldg((const float4*)(A + (size_t)ar * lda + k0 + kq * 4));
            float4 bv = __ldg((const float4*)(B + (size_t)(n0 + row) * K + k0 + kq * 4));
            As[(kq * 4 + 0) * 68 + row] = av.x;
            As[(kq * 4 + 1) * 68 + row] = av.y;
            As[(kq * 4 + 2) * 68 + row] = av.z;
            As[(kq * 4 + 3) * 68 + row] = av.w;
            Bs[(kq * 4 + 0) * 68 + row] = bv.x;
            Bs[(kq * 4 + 1) * 68 + row] = bv.y;
            Bs[(kq * 4 + 2) * 68 + row] = bv.z;
            Bs[(kq * 4 + 3) * 68 + row] = bv.w;
        }
        __syncthreads();
#pragma unroll
        for (int k = 0; k < 32; k++) {
            float4 a4 = *(const float4*)(As + k * 68 + mt);
            float4 b4 = *(const float4*)(Bs + k * 68 + nt);
            float am[4] = {a4.x, a4.y, a4.z, a4.w};
            float bn[4] = {b4.x, b4.y, b4.z, b4.w};
#pragma unroll
            for (int i = 0; i < 4; i++)
#pragma unroll
                for (int j = 0; j < 4; j++) acc[i][j] = fmaf(am[i], bn[j], acc[i][j]);
        }
        __syncthreads();
    }
    float4 b4 = __ldg((const float4*)(bias + n0 + nt));
#pragma unroll
    for (int i = 0; i < 4; i++) {
        float4 r;
        r.x = acc[i][0] + b4.x; r.y = acc[i][1] + b4.y;
        r.z = acc[i][2] + b4.z; r.w = acc[i][3] + b4.w;
        *(float4*)(C + (size_t)(m0 + mt + i) * ldc + n0 + nt) = r;
    }
}

// ---------------- GRU: 4 clusters x 8 CTAs, warp-local step pipeline ----------------
// Thread (d, o) = (dim 0..31, octant 0..7): all 3 gates for dim d over cols
// [32o, 32o+32). Gate sums reduce over the 8 octant lanes IN-WARP; o==0 lane does
// the gate math. No smem handoff, no __syncthreads in the loop — only the cluster
// barrier. h stored octant-strided (36 floats) for conflict-free LDS.128.
__global__ void __launch_bounds__(256, 1) __cluster_dims__(8, 1, 1)
gru_kernel(const float* __restrict__ w_hh, const float* __restrict__ b_hh)
{
    __shared__ __align__(16) float hsm[2][8 * 36];   // octant-strided, double-buffered

    const int tid = threadIdx.x;
    const int batch = blockIdx.x >> 3;
    const int rank = blockIdx.x & 7;
    const int d = tid >> 3;          // dim within CTA
    const int o = tid & 7;           // octant (32 cols)
    const int dim0 = rank * 32;

    // weights: 3 gates x 32 cols each, packed f32x2 (96 regs)
    u64 w2[48];
#pragma unroll
    for (int g = 0; g < 3; g++) {
        const float4* ws =
            (const float4*)(w_hh + (size_t)(g * 256 + dim0 + d) * 256 + o * 32);
#pragma unroll
        for (int c = 0; c < 8; c++) {
            float4 v = __ldg(&ws[c]);
            w2[g * 16 + 2 * c]     = pack2(v.x, v.y);
            w2[g * 16 + 2 * c + 1] = pack2(v.z, v.w);
        }
    }
    const float bhr = __ldg(&b_hh[0 * 256 + dim0 + d]);
    const float bhz = __ldg(&b_hh[1 * 256 + dim0 + d]);
    const float bhn = __ldg(&b_hh[2 * 256 + dim0 + d]);

    // initial h -> hsm[0] (own copy of the full 256-dim h)
    for (int idx = tid; idx < HH; idx += 256)
        hsm[0][(idx >> 5) * 36 + (idx & 31)] = g_h[batch * HH + idx];

    const int myd = dim0 + d;
    const int slot = (myd >> 5) * 36 + (myd & 31);
    float xr = 0.f, xz = 0.f, xn = 0.f;
    if (o == 0) {                    // prefetch xp for t=0
        const float* xp = g_xp + (size_t)(batch * TT) * 768 + myd;
        xr = __ldg(xp); xz = __ldg(xp + 256); xn = __ldg(xp + 512);
    }
    __syncthreads();

    for (int t = 0; t < TT; t++) {
        const int rb = t & 1, wb = rb ^ 1;

        // my 32-col slice of h: 8 conflict-free LDS.128
        u64 hv[16];
        {
            const ulonglong2* hs2 = (const ulonglong2*)(hsm[rb] + o * 36);
#pragma unroll
            for (int c = 0; c < 8; c++) {
                ulonglong2 p = hs2[c];
                hv[2 * c] = p.x; hv[2 * c + 1] = p.y;
            }
        }
        const float hold = hsm[rb][slot];     // broadcast within octant group

        u64 ar0 = 0, ar1 = 0, az0 = 0, az1 = 0, an0 = 0, an1 = 0;
#pragma unroll
        for (int c = 0; c < 16; c += 2) {
            ar0 = ffma2(w2[c],          hv[c],     ar0);
            ar1 = ffma2(w2[c + 1],      hv[c + 1], ar1);
            az0 = ffma2(w2[16 + c],     hv[c],     az0);
            az1 = ffma2(w2[16 + c + 1], hv[c + 1], az1);
            an0 = ffma2(w2[32 + c],     hv[c],     an0);
            an1 = ffma2(w2[32 + c + 1], hv[c + 1], an1);
        }
        float p0, p1, p2, p3;
        unpack2(ar0, p0, p1); unpack2(ar1, p2, p3);
        float sr = (p0 + p1) + (p2 + p3);
        unpack2(az0, p0, p1); unpack2(az1, p2, p3);
        float sz = (p0 + p1) + (p2 + p3);
        unpack2(an0, p0, p1); unpack2(an1, p2, p3);
        float sn = (p0 + p1) + (p2 + p3);
#pragma unroll
        for (int off = 1; off < 8; off <<= 1) {
            sr += __shfl_xor_sync(0xffffffffu, sr, off);
            sz += __shfl_xor_sync(0xffffffffu, sz, off);
            sn += __shfl_xor_sync(0xffffffffu, sn, off);
        }

        if (o == 0) {
            const float hr = sr + bhr, hz = sz + bhz, hn = sn + bhn;
            // sigmoid(x) = 0.5 + 0.5*tanh(x/2): one MUFU per gate
            const float r = fmaf(0.5f, tanh_fast(0.5f * (xr + hr)), 0.5f);
            const float z = fmaf(0.5f, tanh_fast(0.5f * (xz + hz)), 0.5f);
            const float n = tanh_fast(fmaf(r, hn, xn));
            const float hnew = fmaf(z, hold - n, n);    // (1-z)*n + z*h
            g_combined[(size_t)(batch * TT + t) * 512 + myd] = hnew;

            // broadcast to hsm[wb] of all 8 cluster CTAs (disjoint slots)
            const uint32_t laddr = smem_u32(&hsm[wb][slot]);
#pragma unroll
            for (int pr = 0; pr < 8; pr++) {
                uint32_t raddr;
                asm("mapa.shared::cluster.u32 %0, %1, %2;"
                    : "=r"(raddr) : "r"(laddr), "r"(pr));
                asm volatile("st.shared::cluster.f32 [%0], %1;"
                             :: "r"(raddr), "f"(hnew));
            }
            if (t + 1 < TT) {                  // prefetch next xp
                const float* xp = g_xp + (size_t)(batch * TT + t + 1) * 768 + myd;
                xr = __ldg(xp); xz = __ldg(xp + 256); xn = __ldg(xp + 512);
            }
        }
        // cluster barrier: release my DSMEM stores, acquire peers'
        asm volatile("barrier.cluster.arrive.aligned;" ::: "memory");
        asm volatile("barrier.cluster.wait.aligned;" ::: "memory");
    }

    if (o == 0)                                // step TT lands in buffer 0
        g_h[batch * HH + myd] = hsm[0][slot];
}

// ---------------- attention ----------------
__global__ void __launch_bounds__(256) attn_kernel(
    const float* __restrict__ vW, const float* __restrict__ vb)
{
    __shared__ float tile[16 * 256];
    __shared__ float sc[8][512];

    const int tid = threadIdx.x;
    const int w = tid >> 5, lane = tid & 31;
    const int b = blockIdx.y, it = blockIdx.x;
    const int i = it * 8 + w;

    const float4* q4 = (const float4*)(g_q + (size_t)(b * TT + i) * HH + lane * 8);
    const float4 q0 = __ldg(q4), q1 = __ldg(q4 + 1);
    const float4* v4 = (const float4*)(vW + lane * 8);
    const float4 v0 = __ldg(v4), v1 = __ldg(v4 + 1);
    const float vbias = __ldg(vb);

    const int imax = it * 8 + 7;
    const int ntiles = (imax >> 4) + 1;

    for (int jt = 0; jt < ntiles; jt++) {
        const int j0 = jt * 16;
        float4* t4 = (float4*)tile;
#pragma unroll
        for (int rep = 0; rep < 4; rep++) {
            int f = tid + rep * 256;
            int row = f >> 6, c4 = f & 63;
            t4[f] = __ldg((const float4*)g_k + (size_t)(b * TT + j0 + row) * 64 + c4);
        }
        __syncthreads();
#pragma unroll 4
        for (int jj = 0; jj < 16; jj++) {
            int j = j0 + jj;
            if (j <= i) {
                const float4* kr = (const float4*)(tile + jj * 256) + lane * 2;
                float4 k0 = kr[0], k1 = kr[1];
                float s;
                s = v0.x * tanh_fast(q0.x + k0.x);
                s = fmaf(v0.y, tanh_fast(q0.y + k0.y), s);
                s = fmaf(v0.z, tanh_fast(q0.z + k0.z), s);
                s = fmaf(v0.w, tanh_fast(q0.w + k0.w), s);
                s = fmaf(v1.x, tanh_fast(q1.x + k1.x), s);
                s = fmaf(v1.y, tanh_fast(q1.y + k1.y), s);
                s = fmaf(v1.z, tanh_fast(q1.z + k1.z), s);
                s = fmaf(v1.w, tanh_fast(q1.w + k1.w), s);
#pragma unroll
                for (int o = 16; o > 0; o >>= 1) s += __shfl_xor_sync(0xffffffffu, s, o);
                if (lane == 0) sc[w][j] = s + vbias;
            }
        }
        __syncthreads();
    }

    float m = -1e30f;
    for (int j = lane; j <= i; j += 32) m = fmaxf(m, sc[w][j]);
#pragma unroll
    for (int o = 16; o > 0; o >>= 1) m = fmaxf(m, __shfl_xor_sync(0xffffffffu, m, o));
    float sum = 0.f;
    for (int j = lane; j <= i; j += 32) {
        float p = __expf(sc[w][j] - m);
        sc[w][j] = p;
        sum += p;
    }
#pragma unroll
    for (int o = 16; o > 0; o >>= 1) sum += __shfl_xor_sync(0xffffffffu, sum, o);
    const float inv = 1.f / sum;
    __syncthreads();

    float a0 = 0, a1 = 0, a2 = 0, a3 = 0, a4 = 0, a5 = 0, a6 = 0, a7 = 0;
    for (int jt = 0; jt < ntiles; jt++) {
        const int j0 = jt * 16;
        float4* t4 = (float4*)tile;
#pragma unroll
        for (int rep = 0; rep < 4; rep++) {
            int f = tid + rep * 256;
            int row = f >> 6, c4 = f & 63;
            t4[f] = __ldg((const float4*)g_combined + (size_t)(b * TT + j0 + row) * 128 + c4);
        }
        __syncthreads();
#pragma unroll 4
        for (int jj = 0; jj < 16; jj++) {
            int j = j0 + jj;
            if (j <= i) {
                float p = sc[w][j];
                const float4* orow = (const float4*)(tile + jj * 256) + lane * 2;
                float4 o0 = orow[0], o1 = orow[1];
                a0 = fmaf(p, o0.x, a0); a1 = fmaf(p, o0.y, a1);
                a2 = fmaf(p, o0.z, a2); a3 = fmaf(p, o0.w, a3);
                a4 = fmaf(p, o1.x, a4); a5 = fmaf(p, o1.y, a5);
                a6 = fmaf(p, o1.z, a6); a7 = fmaf(p, o1.w, a7);
            }
        }
        __syncthreads();
    }
    float* dst = g_combined + (size_t)(b * TT + i) * 512 + 256 + lane * 8;
    float4 r0 = {a0 * inv, a1 * inv, a2 * inv, a3 * inv};
    float4 r1 = {a4 * inv, a5 * inv, a6 * inv, a7 * inv};
    *(float4*)dst = r0;
    *(float4*)(dst + 4) = r1;
}

// ---------------- split-bf16 conversions ----------------
__global__ void __launch_bounds__(256) convW_kernel(const float* __restrict__ W) {
    size_t i = ((size_t)blockIdx.x * 256 + threadIdx.x) * 4;
    float4 v = __ldg((const float4*)(W + i));
    __nv_bfloat16 h[4], l[4];
    float x[4] = {v.x, v.y, v.z, v.w};
#pragma unroll
    for (int j = 0; j < 4; j++) {
        h[j] = __float2bfloat16(x[j]);
        l[j] = __float2bfloat16(x[j] - __bfloat162float(h[j]));
    }
    *(uint2*)(g_Whi + i) = *(uint2*)h;
    *(uint2*)(g_Wlo + i) = *(uint2*)l;
}

__global__ void __launch_bounds__(256) convA_kernel() {
    size_t i = ((size_t)blockIdx.x * 256 + threadIdx.x) * 4;
    float4 v = *(const float4*)(g_combined + i);
    __nv_bfloat16 h[4], l[4];
    float x[4] = {v.x, v.y, v.z, v.w};
#pragma unroll
    for (int j = 0; j < 4; j++) {
        h[j] = __float2bfloat16(x[j]);
        l[j] = __float2bfloat16(x[j] - __bfloat162float(h[j]));
    }
    *(uint2*)(g_Ahi + i) = *(uint2*)h;
    *(uint2*)(g_Alo + i) = *(uint2*)l;
}

// ---------------- FC via mma.sync HMMA ----------------
// C[2048,32000] = Ahi@Whi^T + Ahi@Wlo^T + Alo@Whi^T + bias  (split-bf16, fp32 accum).
// CTA 128x128x32, 256 threads, 8 warps (2m x 4n), warp tile 64x32, 2 CTAs/SM.
#define FC_BM 128
#define FC_BN 128
#define ROWB 80
#define FC_STAGE ((FC_BM + FC_BN) * ROWB)      // 20480
#define FC_SMEM (2 * FC_STAGE)                 // 40960

__device__ __forceinline__ void ldmatrix_x4(uint32_t& r0, uint32_t& r1, uint32_t& r2,
                                            uint32_t& r3, uint32_t addr) {
    asm volatile("ldmatrix.sync.aligned.m8n8.x4.shared.b16 {%0,%1,%2,%3}, [%4];"
                 : "=r"(r0), "=r"(r1), "=r"(r2), "=r"(r3) : "r"(addr));
}
__device__ __forceinline__ void mma16816(float* d, const uint32_t* a, const uint32_t* b) {
    asm volatile(
        "mma.sync.aligned.m16n8k16.row.col.f32.bf16.bf16.f32 "
        "{%0,%1,%2,%3}, {%4,%5,%6,%7}, {%8,%9}, {%0,%1,%2,%3};"
        : "+f"(d[0]), "+f"(d[1]), "+f"(d[2]), "+f"(d[3])
        : "r"(a[0]), "r"(a[1]), "r"(a[2]), "r"(a[3]), "r"(b[0]), "r"(b[1]));
}
__device__ __forceinline__ void cp_async16(uint32_t dst, const void* src) {
    asm volatile("cp.async.cg.shared.global [%0], [%1], 16;" :: "r"(dst), "l"(src));
}

__global__ void __launch_bounds__(256, 2) fc_mma_kernel(
    const float* __restrict__ bias, float* __restrict__ C)
{
    extern __shared__ __align__(128) char smem[];
    const int tid = threadIdx.x;
    const int lane = tid & 31, warp = tid >> 5;
    const int wm = warp >> 2, wn = warp & 3;
    const int mBase = wm * 64, nBase = wn * 32;
    const int m0 = blockIdx.y * FC_BM, n0 = blockIdx.x * FC_BN;
    const uint32_t sm_base = smem_u32(smem);

    float acc[4][4][4];
#pragma unroll
    for (int i = 0; i < 4; i++)
#pragma unroll
        for (int j = 0; j < 4; j++)
#pragma unroll
            for (int r = 0; r < 4; r++) acc[i][j][r] = 0.f;

    auto load_stage = [&](int kc, int buf) {
        const int s = kc >> 4;
        const int kloc = (kc & 15) * 32;
        const __nv_bfloat16* Asrc = (s == 2) ? g_Alo : g_Ahi;
        const __nv_bfloat16* Bsrc = (s == 1) ? g_Wlo : g_Whi;
        const uint32_t base = sm_base + buf * FC_STAGE;
#pragma unroll
        for (int rep = 0; rep < 4; rep++) {
            int f = tid + rep * 256;
            if (f < 512) {
                int row = f >> 2, q = f & 3;
                cp_async16(base + row * ROWB + q * 16,
                           Asrc + (size_t)(m0 + row) * 512 + kloc + q * 8);
            } else {
                int g = f - 512;
                int row = g >> 2, q = g & 3;
                cp_async16(base + FC_BM * ROWB + row * ROWB + q * 16,
                           Bsrc + (size_t)(n0 + row) * 512 + kloc + q * 8);
            }
        }
        asm volatile("cp.async.commit_group;" ::: "memory");
    };

    load_stage(0, 0);

    for (int kc = 0; kc < 48; kc++) {
        const int buf = kc & 1;
        __syncthreads();
        if (kc + 1 < 48) {
            load_stage(kc + 1, buf ^ 1);
            asm volatile("cp.async.wait_group 1;" ::: "memory");
        } else {
            asm volatile("cp.async.wait_group 0;" ::: "memory");
        }
        __syncthreads();

        const uint32_t aSm = sm_base + buf * FC_STAGE;
        const uint32_t bSm = aSm + FC_BM * ROWB;
#pragma unroll
        for (int ks = 0; ks < 2; ks++) {
            const int kofsA = ks * 32 + (lane >> 4) * 16;
            const int kofsB = ks * 32 + ((lane >> 3) & 1) * 16;
            uint32_t a[4][4];
#pragma unroll
            for (int mf = 0; mf < 4; mf++) {
                int row = mBase + mf * 16 + (lane & 15);
                ldmatrix_x4(a[mf][0], a[mf][1], a[mf][2], a[mf][3],
                            aSm + row * ROWB + kofsA);
            }
            uint32_t b[4][2];
#pragma unroll
            for (int nf2 = 0; nf2 < 2; nf2++) {
                int row = nBase + nf2 * 16 + (lane & 7) + ((lane >> 4) << 3);
                uint32_t r0, r1, r2, r3;
                ldmatrix_x4(r0, r1, r2, r3, bSm + row * ROWB + kofsB);
                b[nf2 * 2 + 0][0] = r0; b[nf2 * 2 + 0][1] = r1;
                b[nf2 * 2 + 1][0] = r2; b[nf2 * 2 + 1][1] = r3;
            }
#pragma unroll
            for (int mf = 0; mf < 4; mf++)
#pragma unroll
                for (int nf = 0; nf < 4; nf++)
                    mma16816(acc[mf][nf], a[mf], b[nf]);
        }
    }

    const int mrow = m0 + mBase + (lane >> 2);
    const int ncol = n0 + nBase + (lane & 3) * 2;
    float bb[4][2];
#pragma unroll
    for (int nf = 0; nf < 4; nf++) {
        bb[nf][0] = __ldg(&bias[ncol + nf * 8]);
        bb[nf][1] = __ldg(&bias[ncol + nf * 8 + 1]);
    }
#pragma unroll
    for (int mf = 0; mf < 4; mf++) {
        float* r0p = C + (size_t)(mrow + mf * 16) * VV + ncol;
        float* r1p = C + (size_t)(mrow + mf * 16 + 8) * VV + ncol;
#pragma unroll
        for (int nf = 0; nf < 4; nf++) {
            float2 v0 = {acc[mf][nf][0] + bb[nf][0], acc[mf][nf][1] + bb[nf][1]};
            float2 v1 = {acc[mf][nf][2] + bb[nf][0], acc[mf][nf][3] + bb[nf][1]};
            *(float2*)(r0p + nf * 8) = v0;
            *(float2*)(r1p + nf * 8) = v1;
        }
    }
}

// ---------------- h_last copy ----------------
__global__ void hlast_kernel(float* __restrict__ dst) {
    int t = threadIdx.x;
    if (t < BB * HH) dst[t] = g_h[t];
}

// ---------------- launch ----------------
extern "C" void kernel_launch(void* const* d_in, const int* in_sizes, int n_in,
                              void* d_out, int out_size) {
    const int*   x        = (const int*)  d_in[0];
    const float* h_in     = (const float*)d_in[1];
    const float* embed_W  = (const float*)d_in[2];
    const float* gru_w_ih = (const float*)d_in[3];
    const float* gru_b_ih = (const float*)d_in[4];
    const float* gru_w_hh = (const float*)d_in[5];
    const float* gru_b_hh = (const float*)d_in[6];
    const float* attn_w_W = (const float*)d_in[7];
    const float* attn_w_b = (const float*)d_in[8];
    const float* attn_u_W = (const float*)d_in[9];
    const float* attn_u_b = (const float*)d_in[10];
    const float* attn_v_W = (const float*)d_in[11];
    const float* attn_v_b = (const float*)d_in[12];
    const float* fc_W     = (const float*)d_in[13];
    const float* fc_b     = (const float*)d_in[14];
    float* out = (float*)d_out;

    float* d_xp;       cudaGetSymbolAddress((void**)&d_xp, g_xp);
    float* d_comb;     cudaGetSymbolAddress((void**)&d_comb, g_combined);
    float* d_q;        cudaGetSymbolAddress((void**)&d_q, g_q);
    float* d_k;        cudaGetSymbolAddress((void**)&d_k, g_k);

    cudaFuncSetAttribute(fc_mma_kernel, cudaFuncAttributeMaxDynamicSharedMemorySize,
                         FC_SMEM);

    // 0. W -> bf16 hi/lo split
    convW_kernel<<<(VV * 512) / 1024, 256>>>(fc_W);

    // 1. h0 <- input h
    init_kernel<<<1, 1024>>>(h_in);

    // 2. xp = embed_W[x] @ gru_w_ih^T + b_ih
    gemm_nt<<<dim3(768 / 64, BT / 64), 256>>>(embed_W, EE, x, gru_w_ih, EE,
                                              gru_b_ih, d_xp, 768);

    // 3. GRU scan: 4 clusters of 8 CTAs (writes combined[:, :256])
    gru_kernel<<<32, 256>>>(gru_w_hh, gru_b_hh);

    // 4. q, k projections
    gemm_nt<<<dim3(HH / 64, BT / 64), 256>>>(d_comb, 512, nullptr, attn_w_W, HH,
                                             attn_w_b, d_q, HH);
    gemm_nt<<<dim3(HH / 64, BT / 64), 256>>>(d_comb, 512, nullptr, attn_u_W, HH,
                                             attn_u_b, d_k, HH);

    // 5. attention (writes combined[:, 256:])
    attn_kernel<<<dim3(TT / 8, BB), 256>>>(attn_v_W, attn_v_b);

    // 6. combined -> bf16 hi/lo split
    convA_kernel<<<(BT * 512) / 1024, 256>>>();

    // 7. logits via HMMA (128x128 tiles, 2 CTAs/SM)
    fc_mma_kernel<<<dim3(VV / FC_BN, BT / FC_BM), 256, FC_SMEM>>>(fc_b, out);

    // 8. h_last
    hlast_kernel<<<1, 1024>>>(out + (size_t)out_size - BB * HH);
}